// round 1
// baseline (speedup 1.0000x reference)
#include <cuda_runtime.h>
#include <cuda_bf16.h>
#include <mma.h>

using namespace nvcuda;

#define B_  2
#define L_  2048
#define D_  1024
#define H_  16
#define HD_ 64
#define M_  (B_ * L_)   // 4096

// Scratch (static __device__ arrays: allocation-free per harness rules)
__device__ float g_Qp[B_ * H_ * L_ * HD_];
__device__ float g_Kp[B_ * H_ * L_ * HD_];
__device__ float g_Vp[B_ * H_ * L_ * HD_];
__device__ float g_AO[B_ * H_ * L_ * HD_];

// ---------------------------------------------------------------------------
// Fused Q/K/V projection: Y = X @ W^T + b, written head-split [B,H,L,HD].
// blockIdx.z selects (X, W, b, out). Tile 128x128x32, 8 warps (2x4), TF32 wmma.
// ---------------------------------------------------------------------------
__global__ __launch_bounds__(256) void proj_kernel(
    const float* __restrict__ q, const float* __restrict__ k, const float* __restrict__ v,
    const float* __restrict__ Wq, const float* __restrict__ bq,
    const float* __restrict__ Wk, const float* __restrict__ bk,
    const float* __restrict__ Wv, const float* __restrict__ bv)
{
    extern __shared__ char smem[];
    float* As = (float*)smem;                     // [128][36]
    float* Bs = (float*)(smem + 128 * 36 * 4);    // [128][36]
    float* Cs = (float*)smem;                     // [128][132] (epilogue, overlaps A/B)

    const int z = blockIdx.z;
    const float* X    = (z == 0) ? q  : (z == 1) ? k  : v;
    const float* W    = (z == 0) ? Wq : (z == 1) ? Wk : Wv;
    const float* bias = (z == 0) ? bq : (z == 1) ? bk : bv;
    float* outp       = (z == 0) ? g_Qp : (z == 1) ? g_Kp : g_Vp;

    const int m0 = blockIdx.x * 128;
    const int n0 = blockIdx.y * 128;
    const int tid = threadIdx.x;
    const int warp = tid >> 5;
    const int wm = (warp >> 2) * 64;   // 2 warps in M
    const int wn = (warp & 3) * 32;    // 4 warps in N

    wmma::fragment<wmma::accumulator, 16, 16, 8, float> acc[4][2];
    #pragma unroll
    for (int i = 0; i < 4; i++)
        #pragma unroll
        for (int j = 0; j < 2; j++) wmma::fill_fragment(acc[i][j], 0.0f);

    for (int k0 = 0; k0 < D_; k0 += 32) {
        #pragma unroll
        for (int it = 0; it < 4; it++) {
            int idx = tid + it * 256;           // 0..1023
            int r = idx >> 3;
            int c4 = (idx & 7) * 4;
            float4 va = *(const float4*)(X + (size_t)(m0 + r) * D_ + k0 + c4);
            float* dst = As + r * 36 + c4;
            dst[0] = wmma::__float_to_tf32(va.x);
            dst[1] = wmma::__float_to_tf32(va.y);
            dst[2] = wmma::__float_to_tf32(va.z);
            dst[3] = wmma::__float_to_tf32(va.w);
            float4 vb = *(const float4*)(W + (size_t)(n0 + r) * D_ + k0 + c4);
            float* dstb = Bs + r * 36 + c4;
            dstb[0] = wmma::__float_to_tf32(vb.x);
            dstb[1] = wmma::__float_to_tf32(vb.y);
            dstb[2] = wmma::__float_to_tf32(vb.z);
            dstb[3] = wmma::__float_to_tf32(vb.w);
        }
        __syncthreads();

        #pragma unroll
        for (int kk = 0; kk < 4; kk++) {
            wmma::fragment<wmma::matrix_a, 16, 16, 8, wmma::precision::tf32, wmma::row_major> af[4];
            wmma::fragment<wmma::matrix_b, 16, 16, 8, wmma::precision::tf32, wmma::col_major> bf[2];
            #pragma unroll
            for (int i = 0; i < 4; i++)
                wmma::load_matrix_sync(af[i], As + (wm + i * 16) * 36 + kk * 8, 36);
            #pragma unroll
            for (int j = 0; j < 2; j++)
                wmma::load_matrix_sync(bf[j], Bs + (wn + j * 16) * 36 + kk * 8, 36);
            #pragma unroll
            for (int i = 0; i < 4; i++)
                #pragma unroll
                for (int j = 0; j < 2; j++)
                    wmma::mma_sync(acc[i][j], af[i], bf[j], acc[i][j]);
        }
        __syncthreads();
    }

    #pragma unroll
    for (int i = 0; i < 4; i++)
        #pragma unroll
        for (int j = 0; j < 2; j++)
            wmma::store_matrix_sync(Cs + (wm + i * 16) * 132 + wn + j * 16, acc[i][j],
                                    132, wmma::mem_row_major);
    __syncthreads();

    #pragma unroll 8
    for (int it = 0; it < 64; it++) {
        int idx = tid + it * 256;     // 0..16383
        int r = idx >> 7;
        int c = idx & 127;
        int m = m0 + r, n = n0 + c;
        int b = m >> 11, l = m & (L_ - 1);
        int h = n >> 6, hd = n & (HD_ - 1);
        outp[(((size_t)(b * H_ + h)) * L_ + l) * HD_ + hd] = Cs[r * 132 + c] + bias[n];
    }
}

// ---------------------------------------------------------------------------
// Flash attention: one CTA = 64 queries x one (b,h). Online softmax, O in smem.
// ---------------------------------------------------------------------------
__global__ __launch_bounds__(256) void attn_kernel(const unsigned char* __restrict__ mask)
{
    extern __shared__ char smem[];
    float* Qs = (float*)smem;            // 64x68 (tf32)
    float* Ks = Qs + 64 * 68;            // 64x68 (tf32)
    float* Vs = Ks + 64 * 68;            // 64x68 (tf32)
    float* Ss = Vs + 64 * 68;            // 64x68 (scores, then P as tf32)
    float* Os = Ss + 64 * 68;            // 64x68 fp32 accumulator
    float* mrow = Os + 64 * 68;          // 64
    float* lrow = mrow + 64;             // 64
    float* madd = lrow + 64;             // 64

    const int q0 = blockIdx.x * 64;
    const int bh = blockIdx.y;           // b*H + h
    const int b  = bh >> 4;
    const int tid = threadIdx.x;
    const int warp = tid >> 5;
    const float scale = 0.125f;          // 1/sqrt(64)

    // Load Q tile
    const float* Qg = g_Qp + ((size_t)bh * L_ + q0) * HD_;
    #pragma unroll
    for (int it = 0; it < 4; it++) {
        int idx = tid + it * 256;        // 0..1023
        int r = idx >> 4;
        int c4 = (idx & 15) * 4;
        float4 vq = *(const float4*)(Qg + r * HD_ + c4);
        float* dst = Qs + r * 68 + c4;
        dst[0] = wmma::__float_to_tf32(vq.x);
        dst[1] = wmma::__float_to_tf32(vq.y);
        dst[2] = wmma::__float_to_tf32(vq.z);
        dst[3] = wmma::__float_to_tf32(vq.w);
    }
    for (int it = tid; it < 64 * 68; it += 256) Os[it] = 0.0f;
    if (tid < 64) { mrow[tid] = -1e30f; lrow[tid] = 0.0f; }
    __syncthreads();

    for (int kt = 0; kt < L_ / 64; kt++) {
        const int kbase = kt * 64;
        const float* Kg = g_Kp + ((size_t)bh * L_ + kbase) * HD_;
        const float* Vg = g_Vp + ((size_t)bh * L_ + kbase) * HD_;
        #pragma unroll
        for (int it = 0; it < 4; it++) {
            int idx = tid + it * 256;
            int r = idx >> 4;
            int c4 = (idx & 15) * 4;
            float4 vk = *(const float4*)(Kg + r * HD_ + c4);
            float* dk = Ks + r * 68 + c4;
            dk[0] = wmma::__float_to_tf32(vk.x);
            dk[1] = wmma::__float_to_tf32(vk.y);
            dk[2] = wmma::__float_to_tf32(vk.z);
            dk[3] = wmma::__float_to_tf32(vk.w);
            float4 vv = *(const float4*)(Vg + r * HD_ + c4);
            float* dv = Vs + r * 68 + c4;
            dv[0] = wmma::__float_to_tf32(vv.x);
            dv[1] = wmma::__float_to_tf32(vv.y);
            dv[2] = wmma::__float_to_tf32(vv.z);
            dv[3] = wmma::__float_to_tf32(vv.w);
        }
        if (tid < 64) madd[tid] = mask[b * L_ + kbase + tid] ? -1e30f : 0.0f;
        __syncthreads();

        // S = Q K^T  (64x64), warp tile 16x32, warp grid 4(M) x 2(N)
        {
            const int swm = (warp >> 1) * 16;
            const int swn = (warp & 1) * 32;
            wmma::fragment<wmma::accumulator, 16, 16, 8, float> sacc[2];
            wmma::fill_fragment(sacc[0], 0.0f);
            wmma::fill_fragment(sacc[1], 0.0f);
            #pragma unroll
            for (int kk = 0; kk < 8; kk++) {
                wmma::fragment<wmma::matrix_a, 16, 16, 8, wmma::precision::tf32, wmma::row_major> af;
                wmma::load_matrix_sync(af, Qs + swm * 68 + kk * 8, 68);
                #pragma unroll
                for (int j = 0; j < 2; j++) {
                    wmma::fragment<wmma::matrix_b, 16, 16, 8, wmma::precision::tf32, wmma::col_major> bf;
                    wmma::load_matrix_sync(bf, Ks + (swn + j * 16) * 68 + kk * 8, 68);
                    wmma::mma_sync(sacc[j], af, bf, sacc[j]);
                }
            }
            #pragma unroll
            for (int j = 0; j < 2; j++)
                wmma::store_matrix_sync(Ss + swm * 68 + swn + j * 16, sacc[j], 68,
                                        wmma::mem_row_major);
        }
        __syncthreads();

        // Online softmax: 4 threads per row, 16 cols each
        {
            const int r  = tid >> 2;
            const int qd = tid & 3;
            float* srow = Ss + r * 68 + qd * 16;
            const float mold = mrow[r];
            float sv[16];
            float vmax = -1e30f;
            #pragma unroll
            for (int c = 0; c < 16; c++) {
                sv[c] = srow[c] * scale + madd[qd * 16 + c];
                vmax = fmaxf(vmax, sv[c]);
            }
            vmax = fmaxf(vmax, __shfl_xor_sync(0xffffffffu, vmax, 1));
            vmax = fmaxf(vmax, __shfl_xor_sync(0xffffffffu, vmax, 2));
            const float newm = fmaxf(mold, vmax);
            const float alpha = __expf(mold - newm);
            float psum = 0.0f;
            #pragma unroll
            for (int c = 0; c < 16; c++) {
                float p = __expf(sv[c] - newm);
                psum += p;
                srow[c] = wmma::__float_to_tf32(p);
            }
            psum += __shfl_xor_sync(0xffffffffu, psum, 1);
            psum += __shfl_xor_sync(0xffffffffu, psum, 2);
            if (qd == 0) {
                mrow[r] = newm;
                lrow[r] = lrow[r] * alpha + psum;
            }
            float* orow = Os + r * 68 + qd * 16;
            #pragma unroll
            for (int c = 0; c < 16; c++) orow[c] *= alpha;
        }
        __syncthreads();

        // O += P @ V
        {
            const int swm = (warp >> 1) * 16;
            const int swn = (warp & 1) * 32;
            wmma::fragment<wmma::accumulator, 16, 16, 8, float> oacc[2];
            #pragma unroll
            for (int j = 0; j < 2; j++)
                wmma::load_matrix_sync(oacc[j], Os + swm * 68 + swn + j * 16, 68,
                                       wmma::mem_row_major);
            #pragma unroll
            for (int kk = 0; kk < 8; kk++) {
                wmma::fragment<wmma::matrix_a, 16, 16, 8, wmma::precision::tf32, wmma::row_major> af;
                wmma::load_matrix_sync(af, Ss + swm * 68 + kk * 8, 68);
                #pragma unroll
                for (int j = 0; j < 2; j++) {
                    wmma::fragment<wmma::matrix_b, 16, 16, 8, wmma::precision::tf32, wmma::row_major> bf;
                    wmma::load_matrix_sync(bf, Vs + kk * 8 * 68 + swn + j * 16, 68);
                    wmma::mma_sync(oacc[j], af, bf, oacc[j]);
                }
            }
            #pragma unroll
            for (int j = 0; j < 2; j++)
                wmma::store_matrix_sync(Os + swm * 68 + swn + j * 16, oacc[j], 68,
                                        wmma::mem_row_major);
        }
        __syncthreads();
    }

    // Finalize: divide by l, write to scratch [B,H,L,HD]
    {
        const int r  = tid >> 2;
        const int qd = tid & 3;
        const float lr = lrow[r];
        const float inv = (lr > 0.0f) ? 1.0f / lr : 0.0f;
        const float* orow = Os + r * 68 + qd * 16;
        float* og = g_AO + ((size_t)bh * L_ + q0 + r) * HD_ + qd * 16;
        #pragma unroll
        for (int c = 0; c < 16; c++) og[c] = orow[c] * inv;
    }
}

// ---------------------------------------------------------------------------
// Output projection: out = AO_merged @ Wo^T + bo. A-tile gathered from
// head-split layout; output dense [B,L,D].
// ---------------------------------------------------------------------------
__global__ __launch_bounds__(256) void oproj_kernel(
    const float* __restrict__ Wo, const float* __restrict__ bo, float* __restrict__ out)
{
    extern __shared__ char smem[];
    float* As = (float*)smem;
    float* Bs = (float*)(smem + 128 * 36 * 4);
    float* Cs = (float*)smem;

    const int m0 = blockIdx.x * 128;
    const int n0 = blockIdx.y * 128;
    const int tid = threadIdx.x;
    const int warp = tid >> 5;
    const int wm = (warp >> 2) * 64;
    const int wn = (warp & 3) * 32;

    wmma::fragment<wmma::accumulator, 16, 16, 8, float> acc[4][2];
    #pragma unroll
    for (int i = 0; i < 4; i++)
        #pragma unroll
        for (int j = 0; j < 2; j++) wmma::fill_fragment(acc[i][j], 0.0f);

    for (int k0 = 0; k0 < D_; k0 += 32) {
        const int head = k0 >> 6;
        const int koff = k0 & (HD_ - 1);
        #pragma unroll
        for (int it = 0; it < 4; it++) {
            int idx = tid + it * 256;
            int r = idx >> 3;
            int c4 = (idx & 7) * 4;
            int m = m0 + r;
            int b = m >> 11, l = m & (L_ - 1);
            float4 va = *(const float4*)(g_AO +
                (((size_t)(b * H_ + head)) * L_ + l) * HD_ + koff + c4);
            float* dst = As + r * 36 + c4;
            dst[0] = wmma::__float_to_tf32(va.x);
            dst[1] = wmma::__float_to_tf32(va.y);
            dst[2] = wmma::__float_to_tf32(va.z);
            dst[3] = wmma::__float_to_tf32(va.w);
            float4 vb = *(const float4*)(Wo + (size_t)(n0 + r) * D_ + k0 + c4);
            float* dstb = Bs + r * 36 + c4;
            dstb[0] = wmma::__float_to_tf32(vb.x);
            dstb[1] = wmma::__float_to_tf32(vb.y);
            dstb[2] = wmma::__float_to_tf32(vb.z);
            dstb[3] = wmma::__float_to_tf32(vb.w);
        }
        __syncthreads();

        #pragma unroll
        for (int kk = 0; kk < 4; kk++) {
            wmma::fragment<wmma::matrix_a, 16, 16, 8, wmma::precision::tf32, wmma::row_major> af[4];
            wmma::fragment<wmma::matrix_b, 16, 16, 8, wmma::precision::tf32, wmma::col_major> bf[2];
            #pragma unroll
            for (int i = 0; i < 4; i++)
                wmma::load_matrix_sync(af[i], As + (wm + i * 16) * 36 + kk * 8, 36);
            #pragma unroll
            for (int j = 0; j < 2; j++)
                wmma::load_matrix_sync(bf[j], Bs + (wn + j * 16) * 36 + kk * 8, 36);
            #pragma unroll
            for (int i = 0; i < 4; i++)
                #pragma unroll
                for (int j = 0; j < 2; j++)
                    wmma::mma_sync(acc[i][j], af[i], bf[j], acc[i][j]);
        }
        __syncthreads();
    }

    #pragma unroll
    for (int i = 0; i < 4; i++)
        #pragma unroll
        for (int j = 0; j < 2; j++)
            wmma::store_matrix_sync(Cs + (wm + i * 16) * 132 + wn + j * 16, acc[i][j],
                                    132, wmma::mem_row_major);
    __syncthreads();

    #pragma unroll 8
    for (int it = 0; it < 64; it++) {
        int idx = tid + it * 256;
        int r = idx >> 7;
        int c = idx & 127;
        int m = m0 + r, n = n0 + c;
        out[(size_t)m * D_ + n] = Cs[r * 132 + c] + bo[n];
    }
}

// ---------------------------------------------------------------------------
extern "C" void kernel_launch(void* const* d_in, const int* in_sizes, int n_in,
                              void* d_out, int out_size)
{
    const float* q    = (const float*)d_in[0];
    const float* k    = (const float*)d_in[1];
    const float* v    = (const float*)d_in[2];
    const unsigned char* mask = (const unsigned char*)d_in[3];
    const float* Wq   = (const float*)d_in[4];
    const float* bq   = (const float*)d_in[5];
    const float* Wk   = (const float*)d_in[6];
    const float* bk   = (const float*)d_in[7];
    const float* Wv   = (const float*)d_in[8];
    const float* bv   = (const float*)d_in[9];
    const float* Wo   = (const float*)d_in[10];
    const float* bo   = (const float*)d_in[11];
    float* out        = (float*)d_out;

    const int projSmem = 128 * 132 * 4;               // 67584
    const int attnSmem = (5 * 64 * 68 + 3 * 64) * 4;  // 87808

    cudaFuncSetAttribute(proj_kernel,  cudaFuncAttributeMaxDynamicSharedMemorySize, projSmem);
    cudaFuncSetAttribute(attn_kernel,  cudaFuncAttributeMaxDynamicSharedMemorySize, attnSmem);
    cudaFuncSetAttribute(oproj_kernel, cudaFuncAttributeMaxDynamicSharedMemorySize, projSmem);

    dim3 gProj(M_ / 128, D_ / 128, 3);
    proj_kernel<<<gProj, 256, projSmem>>>(q, k, v, Wq, bq, Wk, bk, Wv, bv);

    dim3 gAttn(L_ / 64, B_ * H_);
    attn_kernel<<<gAttn, 256, attnSmem>>>(mask);

    dim3 gOut(M_ / 128, D_ / 128);
    oproj_kernel<<<gOut, 256, projSmem>>>(Wo, bo, out);
}

// round 2
// speedup vs baseline: 2.1711x; 2.1711x over previous
#include <cuda_runtime.h>
#include <cuda_bf16.h>
#include <mma.h>

using namespace nvcuda;

#define B_  2
#define L_  2048
#define D_  1024
#define H_  16
#define HD_ 64
#define M_  (B_ * L_)   // 4096

// Scratch (static __device__ arrays: allocation-free per harness rules)
__device__ float g_Qp[B_ * H_ * L_ * HD_];
__device__ float g_Kp[B_ * H_ * L_ * HD_];
__device__ float g_Vp[B_ * H_ * L_ * HD_];
__device__ float g_AO[B_ * H_ * L_ * HD_];

// ---------------------------------------------------------------------------
// Fused Q/K/V projection: Y = X @ W^T + b, written head-split [B,H,L,HD].
// ---------------------------------------------------------------------------
__global__ __launch_bounds__(256) void proj_kernel(
    const float* __restrict__ q, const float* __restrict__ k, const float* __restrict__ v,
    const float* __restrict__ Wq, const float* __restrict__ bq,
    const float* __restrict__ Wk, const float* __restrict__ bk,
    const float* __restrict__ Wv, const float* __restrict__ bv)
{
    extern __shared__ char smem[];
    float* As = (float*)smem;                     // [128][36]
    float* Bs = (float*)(smem + 128 * 36 * 4);    // [128][36]
    float* Cs = (float*)smem;                     // [128][132]

    const int z = blockIdx.z;
    const float* X    = (z == 0) ? q  : (z == 1) ? k  : v;
    const float* W    = (z == 0) ? Wq : (z == 1) ? Wk : Wv;
    const float* bias = (z == 0) ? bq : (z == 1) ? bk : bv;
    float* outp       = (z == 0) ? g_Qp : (z == 1) ? g_Kp : g_Vp;

    const int m0 = blockIdx.x * 128;
    const int n0 = blockIdx.y * 128;
    const int tid = threadIdx.x;
    const int warp = tid >> 5;
    const int wm = (warp >> 2) * 64;
    const int wn = (warp & 3) * 32;

    wmma::fragment<wmma::accumulator, 16, 16, 8, float> acc[4][2];
    #pragma unroll
    for (int i = 0; i < 4; i++)
        #pragma unroll
        for (int j = 0; j < 2; j++) wmma::fill_fragment(acc[i][j], 0.0f);

    for (int k0 = 0; k0 < D_; k0 += 32) {
        #pragma unroll
        for (int it = 0; it < 4; it++) {
            int idx = tid + it * 256;
            int r = idx >> 3;
            int c4 = (idx & 7) * 4;
            float4 va = *(const float4*)(X + (size_t)(m0 + r) * D_ + k0 + c4);
            float* dst = As + r * 36 + c4;
            dst[0] = wmma::__float_to_tf32(va.x);
            dst[1] = wmma::__float_to_tf32(va.y);
            dst[2] = wmma::__float_to_tf32(va.z);
            dst[3] = wmma::__float_to_tf32(va.w);
            float4 vb = *(const float4*)(W + (size_t)(n0 + r) * D_ + k0 + c4);
            float* dstb = Bs + r * 36 + c4;
            dstb[0] = wmma::__float_to_tf32(vb.x);
            dstb[1] = wmma::__float_to_tf32(vb.y);
            dstb[2] = wmma::__float_to_tf32(vb.z);
            dstb[3] = wmma::__float_to_tf32(vb.w);
        }
        __syncthreads();

        #pragma unroll
        for (int kk = 0; kk < 4; kk++) {
            wmma::fragment<wmma::matrix_a, 16, 16, 8, wmma::precision::tf32, wmma::row_major> af[4];
            wmma::fragment<wmma::matrix_b, 16, 16, 8, wmma::precision::tf32, wmma::col_major> bf[2];
            #pragma unroll
            for (int i = 0; i < 4; i++)
                wmma::load_matrix_sync(af[i], As + (wm + i * 16) * 36 + kk * 8, 36);
            #pragma unroll
            for (int j = 0; j < 2; j++)
                wmma::load_matrix_sync(bf[j], Bs + (wn + j * 16) * 36 + kk * 8, 36);
            #pragma unroll
            for (int i = 0; i < 4; i++)
                #pragma unroll
                for (int j = 0; j < 2; j++)
                    wmma::mma_sync(acc[i][j], af[i], bf[j], acc[i][j]);
        }
        __syncthreads();
    }

    #pragma unroll
    for (int i = 0; i < 4; i++)
        #pragma unroll
        for (int j = 0; j < 2; j++)
            wmma::store_matrix_sync(Cs + (wm + i * 16) * 132 + wn + j * 16, acc[i][j],
                                    132, wmma::mem_row_major);
    __syncthreads();

    #pragma unroll 8
    for (int it = 0; it < 64; it++) {
        int idx = tid + it * 256;
        int r = idx >> 7;
        int c = idx & 127;
        int m = m0 + r, n = n0 + c;
        int b = m >> 11, l = m & (L_ - 1);
        int h = n >> 6, hd = n & (HD_ - 1);
        outp[(((size_t)(b * H_ + h)) * L_ + l) * HD_ + hd] = Cs[r * 132 + c] + bias[n];
    }
}

// ---------------------------------------------------------------------------
// Flash attention, register-resident. CTA = 128 queries x one (b,h), 8 warps.
// Warp w owns query rows [16w, 16w+16), all 64 HD columns, via mma.m16n8k8 TF32.
// ---------------------------------------------------------------------------
__device__ __forceinline__ void mma_tf32(float c[4], const unsigned a[4],
                                         unsigned b0, unsigned b1)
{
    asm volatile(
        "mma.sync.aligned.m16n8k8.row.col.f32.tf32.tf32.f32 "
        "{%0,%1,%2,%3}, {%4,%5,%6,%7}, {%8,%9}, {%0,%1,%2,%3};"
        : "+f"(c[0]), "+f"(c[1]), "+f"(c[2]), "+f"(c[3])
        : "r"(a[0]), "r"(a[1]), "r"(a[2]), "r"(a[3]), "r"(b0), "r"(b1));
}

#define KPAD 68
#define VPAD 72

__global__ __launch_bounds__(256) void attn_kernel(const unsigned char* __restrict__ mask)
{
    extern __shared__ char smem[];
    float* Ks   = (float*)smem;                     // [64][KPAD]
    float* Vs   = Ks + 64 * KPAD;                   // [64][VPAD]
    float* madd = Vs + 64 * VPAD;                   // [64]

    const int q0   = blockIdx.x * 128;
    const int bh   = blockIdx.y;
    const int b    = bh >> 4;
    const int tid  = threadIdx.x;
    const int warp = tid >> 5;
    const int lane = tid & 31;
    const int qr   = lane >> 2;     // row within quad group (0..7)
    const int qq   = lane & 3;      // quad index (0..3)
    const int rowbase = q0 + warp * 16;
    const float scale = 0.125f;     // 1/sqrt(64)

    // Q fragments (A operand), pre-scaled, persistent in registers.
    unsigned qa[8][4];
    {
        const float* Qg = g_Qp + ((size_t)bh * L_ + rowbase) * HD_;
        #pragma unroll
        for (int ks = 0; ks < 8; ks++) {
            float a0 = Qg[(size_t)qr * HD_ + ks * 8 + qq] * scale;
            float a1 = Qg[(size_t)(qr + 8) * HD_ + ks * 8 + qq] * scale;
            float a2 = Qg[(size_t)qr * HD_ + ks * 8 + qq + 4] * scale;
            float a3 = Qg[(size_t)(qr + 8) * HD_ + ks * 8 + qq + 4] * scale;
            qa[ks][0] = __float_as_uint(wmma::__float_to_tf32(a0));
            qa[ks][1] = __float_as_uint(wmma::__float_to_tf32(a1));
            qa[ks][2] = __float_as_uint(wmma::__float_to_tf32(a2));
            qa[ks][3] = __float_as_uint(wmma::__float_to_tf32(a3));
        }
    }

    float oacc[8][4];
    #pragma unroll
    for (int nt = 0; nt < 8; nt++)
        #pragma unroll
        for (int i = 0; i < 4; i++) oacc[nt][i] = 0.0f;

    float m0 = -1e30f, m1 = -1e30f;   // running max for rows qr, qr+8
    float l0 = 0.0f,  l1 = 0.0f;      // running sums

    const float* Kg0 = g_Kp + (size_t)bh * L_ * HD_;
    const float* Vg0 = g_Vp + (size_t)bh * L_ * HD_;

    for (int kt = 0; kt < L_ / 64; kt++) {
        const int kbase = kt * 64;
        // ---- stage K, V tiles (tf32) ----
        #pragma unroll
        for (int it = 0; it < 4; it++) {
            int idx = tid + it * 256;       // 0..1023
            int key = idx >> 4;
            int c4  = (idx & 15) * 4;
            float4 kv = *(const float4*)(Kg0 + (size_t)(kbase + key) * HD_ + c4);
            float4 ko;
            ko.x = wmma::__float_to_tf32(kv.x); ko.y = wmma::__float_to_tf32(kv.y);
            ko.z = wmma::__float_to_tf32(kv.z); ko.w = wmma::__float_to_tf32(kv.w);
            *(float4*)(Ks + key * KPAD + c4) = ko;
            float4 vv = *(const float4*)(Vg0 + (size_t)(kbase + key) * HD_ + c4);
            float4 vo;
            vo.x = wmma::__float_to_tf32(vv.x); vo.y = wmma::__float_to_tf32(vv.y);
            vo.z = wmma::__float_to_tf32(vv.z); vo.w = wmma::__float_to_tf32(vv.w);
            *(float4*)(Vs + key * VPAD + c4) = vo;
        }
        if (tid < 64) madd[tid] = mask[b * L_ + kbase + tid] ? -1e30f : 0.0f;
        __syncthreads();

        // ---- S = Q K^T (scaled), per-warp 16x64 in C fragments ----
        float sacc[8][4];
        #pragma unroll
        for (int nt = 0; nt < 8; nt++) {
            float c[4] = {0.0f, 0.0f, 0.0f, 0.0f};
            const float* kb = Ks + (nt * 8 + qr) * KPAD;
            #pragma unroll
            for (int ks = 0; ks < 8; ks++) {
                unsigned b0 = __float_as_uint(kb[ks * 8 + qq]);
                unsigned b1 = __float_as_uint(kb[ks * 8 + qq + 4]);
                mma_tf32(c, qa[ks], b0, b1);
            }
            sacc[nt][0] = c[0]; sacc[nt][1] = c[1];
            sacc[nt][2] = c[2]; sacc[nt][3] = c[3];
        }

        // ---- online softmax in registers ----
        float mx0 = -1e30f, mx1 = -1e30f;
        #pragma unroll
        for (int nt = 0; nt < 8; nt++) {
            float ma = madd[nt * 8 + 2 * qq];
            float mb = madd[nt * 8 + 2 * qq + 1];
            sacc[nt][0] += ma; sacc[nt][1] += mb;
            sacc[nt][2] += ma; sacc[nt][3] += mb;
            mx0 = fmaxf(mx0, fmaxf(sacc[nt][0], sacc[nt][1]));
            mx1 = fmaxf(mx1, fmaxf(sacc[nt][2], sacc[nt][3]));
        }
        mx0 = fmaxf(mx0, __shfl_xor_sync(0xffffffffu, mx0, 1));
        mx0 = fmaxf(mx0, __shfl_xor_sync(0xffffffffu, mx0, 2));
        mx1 = fmaxf(mx1, __shfl_xor_sync(0xffffffffu, mx1, 1));
        mx1 = fmaxf(mx1, __shfl_xor_sync(0xffffffffu, mx1, 2));

        float nm0 = fmaxf(m0, mx0), nm1 = fmaxf(m1, mx1);
        float al0 = __expf(m0 - nm0), al1 = __expf(m1 - nm1);
        float ps0 = 0.0f, ps1 = 0.0f;
        #pragma unroll
        for (int nt = 0; nt < 8; nt++) {
            float p0 = __expf(sacc[nt][0] - nm0);
            float p1 = __expf(sacc[nt][1] - nm0);
            float p2 = __expf(sacc[nt][2] - nm1);
            float p3 = __expf(sacc[nt][3] - nm1);
            ps0 += p0 + p1; ps1 += p2 + p3;
            sacc[nt][0] = p0; sacc[nt][1] = p1;
            sacc[nt][2] = p2; sacc[nt][3] = p3;
        }
        ps0 += __shfl_xor_sync(0xffffffffu, ps0, 1);
        ps0 += __shfl_xor_sync(0xffffffffu, ps0, 2);
        ps1 += __shfl_xor_sync(0xffffffffu, ps1, 1);
        ps1 += __shfl_xor_sync(0xffffffffu, ps1, 2);
        l0 = l0 * al0 + ps0;
        l1 = l1 * al1 + ps1;
        m0 = nm0; m1 = nm1;
        #pragma unroll
        for (int nt = 0; nt < 8; nt++) {
            oacc[nt][0] *= al0; oacc[nt][1] *= al0;
            oacc[nt][2] *= al1; oacc[nt][3] *= al1;
        }

        // ---- O += P V : convert P (C layout) -> A layout via quad shuffles ----
        const int srcA = (lane & 28) | (qq >> 1);
        const int srcB = srcA | 2;
        const bool odd = qq & 1;
        #pragma unroll
        for (int ks = 0; ks < 8; ks++) {
            float p0 = sacc[ks][0], p1 = sacc[ks][1];
            float p2 = sacc[ks][2], p3 = sacc[ks][3];
            float v0 = __shfl_sync(0xffffffffu, p0, srcA);
            float v1 = __shfl_sync(0xffffffffu, p1, srcA);
            float v2 = __shfl_sync(0xffffffffu, p2, srcA);
            float v3 = __shfl_sync(0xffffffffu, p3, srcA);
            float w0 = __shfl_sync(0xffffffffu, p0, srcB);
            float w1 = __shfl_sync(0xffffffffu, p1, srcB);
            float w2 = __shfl_sync(0xffffffffu, p2, srcB);
            float w3 = __shfl_sync(0xffffffffu, p3, srcB);
            unsigned pa[4];
            pa[0] = __float_as_uint(odd ? v1 : v0);
            pa[1] = __float_as_uint(odd ? v3 : v2);
            pa[2] = __float_as_uint(odd ? w1 : w0);
            pa[3] = __float_as_uint(odd ? w3 : w2);
            const float* vb0 = Vs + (ks * 8 + qq) * VPAD;
            const float* vb1 = Vs + (ks * 8 + qq + 4) * VPAD;
            #pragma unroll
            for (int nt = 0; nt < 8; nt++) {
                unsigned b0 = __float_as_uint(vb0[nt * 8 + qr]);
                unsigned b1 = __float_as_uint(vb1[nt * 8 + qr]);
                mma_tf32(oacc[nt], pa, b0, b1);
            }
        }
        __syncthreads();
    }

    // ---- finalize: divide by l, write [B,H,L,HD] scratch ----
    {
        float inv0 = (l0 > 0.0f) ? 1.0f / l0 : 0.0f;
        float inv1 = (l1 > 0.0f) ? 1.0f / l1 : 0.0f;
        float* o0 = g_AO + ((size_t)bh * L_ + rowbase + qr) * HD_ + 2 * qq;
        float* o1 = g_AO + ((size_t)bh * L_ + rowbase + qr + 8) * HD_ + 2 * qq;
        #pragma unroll
        for (int nt = 0; nt < 8; nt++) {
            *(float2*)(o0 + nt * 8) = make_float2(oacc[nt][0] * inv0, oacc[nt][1] * inv0);
            *(float2*)(o1 + nt * 8) = make_float2(oacc[nt][2] * inv1, oacc[nt][3] * inv1);
        }
    }
}

// ---------------------------------------------------------------------------
// Output projection: out = AO_merged @ Wo^T + bo.
// ---------------------------------------------------------------------------
__global__ __launch_bounds__(256) void oproj_kernel(
    const float* __restrict__ Wo, const float* __restrict__ bo, float* __restrict__ out)
{
    extern __shared__ char smem[];
    float* As = (float*)smem;
    float* Bs = (float*)(smem + 128 * 36 * 4);
    float* Cs = (float*)smem;

    const int m0 = blockIdx.x * 128;
    const int n0 = blockIdx.y * 128;
    const int tid = threadIdx.x;
    const int warp = tid >> 5;
    const int wm = (warp >> 2) * 64;
    const int wn = (warp & 3) * 32;

    wmma::fragment<wmma::accumulator, 16, 16, 8, float> acc[4][2];
    #pragma unroll
    for (int i = 0; i < 4; i++)
        #pragma unroll
        for (int j = 0; j < 2; j++) wmma::fill_fragment(acc[i][j], 0.0f);

    for (int k0 = 0; k0 < D_; k0 += 32) {
        const int head = k0 >> 6;
        const int koff = k0 & (HD_ - 1);
        #pragma unroll
        for (int it = 0; it < 4; it++) {
            int idx = tid + it * 256;
            int r = idx >> 3;
            int c4 = (idx & 7) * 4;
            int m = m0 + r;
            int b = m >> 11, l = m & (L_ - 1);
            float4 va = *(const float4*)(g_AO +
                (((size_t)(b * H_ + head)) * L_ + l) * HD_ + koff + c4);
            float* dst = As + r * 36 + c4;
            dst[0] = wmma::__float_to_tf32(va.x);
            dst[1] = wmma::__float_to_tf32(va.y);
            dst[2] = wmma::__float_to_tf32(va.z);
            dst[3] = wmma::__float_to_tf32(va.w);
            float4 vb = *(const float4*)(Wo + (size_t)(n0 + r) * D_ + k0 + c4);
            float* dstb = Bs + r * 36 + c4;
            dstb[0] = wmma::__float_to_tf32(vb.x);
            dstb[1] = wmma::__float_to_tf32(vb.y);
            dstb[2] = wmma::__float_to_tf32(vb.z);
            dstb[3] = wmma::__float_to_tf32(vb.w);
        }
        __syncthreads();

        #pragma unroll
        for (int kk = 0; kk < 4; kk++) {
            wmma::fragment<wmma::matrix_a, 16, 16, 8, wmma::precision::tf32, wmma::row_major> af[4];
            wmma::fragment<wmma::matrix_b, 16, 16, 8, wmma::precision::tf32, wmma::col_major> bf[2];
            #pragma unroll
            for (int i = 0; i < 4; i++)
                wmma::load_matrix_sync(af[i], As + (wm + i * 16) * 36 + kk * 8, 36);
            #pragma unroll
            for (int j = 0; j < 2; j++)
                wmma::load_matrix_sync(bf[j], Bs + (wn + j * 16) * 36 + kk * 8, 36);
            #pragma unroll
            for (int i = 0; i < 4; i++)
                #pragma unroll
                for (int j = 0; j < 2; j++)
                    wmma::mma_sync(acc[i][j], af[i], bf[j], acc[i][j]);
        }
        __syncthreads();
    }

    #pragma unroll
    for (int i = 0; i < 4; i++)
        #pragma unroll
        for (int j = 0; j < 2; j++)
            wmma::store_matrix_sync(Cs + (wm + i * 16) * 132 + wn + j * 16, acc[i][j],
                                    132, wmma::mem_row_major);
    __syncthreads();

    #pragma unroll 8
    for (int it = 0; it < 64; it++) {
        int idx = tid + it * 256;
        int r = idx >> 7;
        int c = idx & 127;
        int m = m0 + r, n = n0 + c;
        out[(size_t)m * D_ + n] = Cs[r * 132 + c] + bo[n];
    }
}

// ---------------------------------------------------------------------------
extern "C" void kernel_launch(void* const* d_in, const int* in_sizes, int n_in,
                              void* d_out, int out_size)
{
    const float* q    = (const float*)d_in[0];
    const float* k    = (const float*)d_in[1];
    const float* v    = (const float*)d_in[2];
    const unsigned char* mask = (const unsigned char*)d_in[3];
    const float* Wq   = (const float*)d_in[4];
    const float* bq   = (const float*)d_in[5];
    const float* Wk   = (const float*)d_in[6];
    const float* bk   = (const float*)d_in[7];
    const float* Wv   = (const float*)d_in[8];
    const float* bv   = (const float*)d_in[9];
    const float* Wo   = (const float*)d_in[10];
    const float* bo   = (const float*)d_in[11];
    float* out        = (float*)d_out;

    const int projSmem = 128 * 132 * 4;                       // 67584
    const int attnSmem = (64 * KPAD + 64 * VPAD + 64) * 4;    // 36096

    cudaFuncSetAttribute(proj_kernel,  cudaFuncAttributeMaxDynamicSharedMemorySize, projSmem);
    cudaFuncSetAttribute(attn_kernel,  cudaFuncAttributeMaxDynamicSharedMemorySize, attnSmem);
    cudaFuncSetAttribute(oproj_kernel, cudaFuncAttributeMaxDynamicSharedMemorySize, projSmem);

    dim3 gProj(M_ / 128, D_ / 128, 3);
    proj_kernel<<<gProj, 256, projSmem>>>(q, k, v, Wq, bq, Wk, bk, Wv, bv);

    dim3 gAttn(L_ / 128, B_ * H_);
    attn_kernel<<<gAttn, 256, attnSmem>>>(mask);

    dim3 gOut(M_ / 128, D_ / 128);
    oproj_kernel<<<gOut, 256, projSmem>>>(Wo, bo, out);
}

// round 5
// speedup vs baseline: 2.2667x; 1.0440x over previous
#include <cuda_runtime.h>
#include <cuda_bf16.h>
#include <mma.h>
#include <cstdint>

using namespace nvcuda;

#define B_  2
#define L_  2048
#define D_  1024
#define H_  16
#define HD_ 64
#define M_  (B_ * L_)   // 4096

// Scratch (static __device__ arrays: allocation-free per harness rules)
__device__ float g_Qp[B_ * H_ * L_ * HD_];
__device__ float g_Kp[B_ * H_ * L_ * HD_];
__device__ float g_Vp[B_ * H_ * L_ * HD_];
__device__ float g_AO[B_ * H_ * L_ * HD_];
__device__ float g_Wt[4 * D_ * D_];          // tf32-rounded Wq,Wk,Wv,Wo
__device__ float g_Xt[3 * M_ * D_];          // tf32-rounded q,k,v

// ---------------------------------------------------------------------------
// cp.async helpers
// ---------------------------------------------------------------------------
__device__ __forceinline__ void cpasync16(unsigned int dst, const float* src) {
    asm volatile("cp.async.cg.shared.global [%0], [%1], 16;" :: "r"(dst), "l"(src));
}
__device__ __forceinline__ void cpcommit() {
    asm volatile("cp.async.commit_group;");
}
template<int N> __device__ __forceinline__ void cpwait() {
    asm volatile("cp.async.wait_group %0;" :: "n"(N));
}

// ---------------------------------------------------------------------------
// Pre-pass: round weights + activations to tf32 (RN) once.
// Layout: elems [0, 4M): weights (4 x 1M); [4M, 16M): activations (3 x 4M).
// ---------------------------------------------------------------------------
__global__ __launch_bounds__(256) void prep_kernel(
    const float* __restrict__ q, const float* __restrict__ k, const float* __restrict__ v,
    const float* __restrict__ Wq, const float* __restrict__ Wk,
    const float* __restrict__ Wv, const float* __restrict__ Wo)
{
    const int idx4 = blockIdx.x * 256 + threadIdx.x;   // one float4 each
    const int e = idx4 * 4;
    const float* src;
    float* dst;
    if (e < 4 * D_ * D_) {
        int wsel = e >> 20;
        int off  = e & (D_ * D_ - 1);
        src = ((wsel == 0) ? Wq : (wsel == 1) ? Wk : (wsel == 2) ? Wv : Wo) + off;
        dst = g_Wt + e;
    } else {
        int xe   = e - 4 * D_ * D_;
        int xsel = xe >> 22;
        int off  = xe & (M_ * D_ - 1);
        src = ((xsel == 0) ? q : (xsel == 1) ? k : v) + off;
        dst = g_Xt + xe;
    }
    float4 val = *(const float4*)src;
    val.x = wmma::__float_to_tf32(val.x);
    val.y = wmma::__float_to_tf32(val.y);
    val.z = wmma::__float_to_tf32(val.z);
    val.w = wmma::__float_to_tf32(val.w);
    *(float4*)dst = val;
}

// ---------------------------------------------------------------------------
// Fused Q/K/V projection: Y = X @ W^T + b, head-split output [B,H,L,HD],
// tf32-rounded (Q also pre-scaled by 1/8). 3-stage cp.async pipeline.
// ---------------------------------------------------------------------------
#define NKP (D_ / 32)       // 32 k-iterations
#define STG_F (128 * 36)    // floats per operand tile
#define STG_B (2 * STG_F * 4)  // bytes per stage (A + B)

__global__ __launch_bounds__(256) void proj_kernel(
    const float* __restrict__ bq, const float* __restrict__ bk, const float* __restrict__ bv)
{
    extern __shared__ char smem[];
    const unsigned int smem_u32 = (unsigned int)__cvta_generic_to_shared(smem);
    float* Cs = (float*)smem;   // epilogue reuse [128][132]

    const int z = blockIdx.z;
    const float* X    = g_Xt + (size_t)z * (M_ * D_);
    const float* W    = g_Wt + (size_t)z * (D_ * D_);
    const float* bias = (z == 0) ? bq : (z == 1) ? bk : bv;
    float* outp       = (z == 0) ? g_Qp : (z == 1) ? g_Kp : g_Vp;

    const int m0 = blockIdx.x * 128;
    const int n0 = blockIdx.y * 128;
    const int tid = threadIdx.x;
    const int warp = tid >> 5;
    const int wm = (warp >> 2) * 64;
    const int wn = (warp & 3) * 32;

    const int lr  = tid >> 3;          // 0..31 row group for loads
    const int lc4 = (tid & 7) * 4;     // 0..28 col within k-tile

    wmma::fragment<wmma::accumulator, 16, 16, 8, float> acc[4][2];
    #pragma unroll
    for (int i = 0; i < 4; i++)
        #pragma unroll
        for (int j = 0; j < 2; j++) wmma::fill_fragment(acc[i][j], 0.0f);

    // stage issue: A rows 128 x 32, B rows 128 x 32
    auto issue = [&](int s, int kt) {
        const int k0 = kt * 32;
        const unsigned int sb = smem_u32 + s * STG_B;
        #pragma unroll
        for (int it = 0; it < 4; it++) {
            int r = lr + it * 32;
            cpasync16(sb + (r * 36 + lc4) * 4, X + (size_t)(m0 + r) * D_ + k0 + lc4);
            cpasync16(sb + (STG_F + r * 36 + lc4) * 4, W + (size_t)(n0 + r) * D_ + k0 + lc4);
        }
        cpcommit();
    };

    issue(0, 0);
    issue(1, 1);

    for (int kt = 0; kt < NKP; kt++) {
        if (kt < NKP - 1) { cpwait<1>(); } else { cpwait<0>(); }
        __syncthreads();
        if (kt + 2 < NKP) issue((kt + 2) % 3, kt + 2);

        const float* As = (float*)(smem + (kt % 3) * STG_B);
        const float* Bs = As + STG_F;
        #pragma unroll
        for (int kk = 0; kk < 4; kk++) {
            wmma::fragment<wmma::matrix_a, 16, 16, 8, wmma::precision::tf32, wmma::row_major> af[4];
            wmma::fragment<wmma::matrix_b, 16, 16, 8, wmma::precision::tf32, wmma::col_major> bf[2];
            #pragma unroll
            for (int i = 0; i < 4; i++)
                wmma::load_matrix_sync(af[i], As + (wm + i * 16) * 36 + kk * 8, 36);
            #pragma unroll
            for (int j = 0; j < 2; j++)
                wmma::load_matrix_sync(bf[j], Bs + (wn + j * 16) * 36 + kk * 8, 36);
            #pragma unroll
            for (int i = 0; i < 4; i++)
                #pragma unroll
                for (int j = 0; j < 2; j++)
                    wmma::mma_sync(acc[i][j], af[i], bf[j], acc[i][j]);
        }
        __syncthreads();
    }

    #pragma unroll
    for (int i = 0; i < 4; i++)
        #pragma unroll
        for (int j = 0; j < 2; j++)
            wmma::store_matrix_sync(Cs + (wm + i * 16) * 132 + wn + j * 16, acc[i][j],
                                    132, wmma::mem_row_major);
    __syncthreads();

    const float qscale = (z == 0) ? 0.125f : 1.0f;
    #pragma unroll 8
    for (int it = 0; it < 64; it++) {
        int idx = tid + it * 256;
        int r = idx >> 7;
        int c = idx & 127;
        int m = m0 + r, n = n0 + c;
        int b = m >> 11, l = m & (L_ - 1);
        int h = n >> 6, hd = n & (HD_ - 1);
        float val = wmma::__float_to_tf32(Cs[r * 132 + c] + bias[n]) * qscale;
        outp[(((size_t)(b * H_ + h)) * L_ + l) * HD_ + hd] = val;
    }
}

// ---------------------------------------------------------------------------
// Flash attention, register-resident, 3-stage cp.async K/V pipeline.
// CTA = 128 queries x one (b,h), 8 warps; warp owns 16 rows x 64 cols.
// ---------------------------------------------------------------------------
__device__ __forceinline__ void mma_tf32(float c[4], const unsigned a[4],
                                         unsigned b0, unsigned b1)
{
    asm volatile(
        "mma.sync.aligned.m16n8k8.row.col.f32.tf32.tf32.f32 "
        "{%0,%1,%2,%3}, {%4,%5,%6,%7}, {%8,%9}, {%0,%1,%2,%3};"
        : "+f"(c[0]), "+f"(c[1]), "+f"(c[2]), "+f"(c[3])
        : "r"(a[0]), "r"(a[1]), "r"(a[2]), "r"(a[3]), "r"(b0), "r"(b1));
}

#define KPAD 68
#define VPAD 72
#define ATT_STG_F (64 * KPAD + 64 * VPAD)   // floats per stage
#define ATT_STG_B (ATT_STG_F * 4)
#define NT_ (L_ / 64)                        // 32 key tiles

__global__ __launch_bounds__(256) void attn_kernel(const unsigned char* __restrict__ mask)
{
    extern __shared__ char smem[];
    const unsigned int smem_u32 = (unsigned int)__cvta_generic_to_shared(smem);
    float* Ms = (float*)(smem + 3 * ATT_STG_B);   // [2048] mask adds

    const int q0   = blockIdx.x * 128;
    const int bh   = blockIdx.y;
    const int b    = bh >> 4;
    const int tid  = threadIdx.x;
    const int warp = tid >> 5;
    const int lane = tid & 31;
    const int qr   = lane >> 2;
    const int qq   = lane & 3;
    const int rowbase = q0 + warp * 16;

    const float* Kg0 = g_Kp + (size_t)bh * L_ * HD_;
    const float* Vg0 = g_Vp + (size_t)bh * L_ * HD_;

    // mask row -> float adds, once per CTA
    for (int i = tid; i < L_; i += 256)
        Ms[i] = mask[b * L_ + i] ? -1e30f : 0.0f;

    // Q fragments (already tf32-rounded and scaled by proj)
    unsigned qa[8][4];
    {
        const float* Qg = g_Qp + ((size_t)bh * L_ + rowbase) * HD_;
        #pragma unroll
        for (int ks = 0; ks < 8; ks++) {
            qa[ks][0] = __float_as_uint(Qg[(size_t)qr * HD_ + ks * 8 + qq]);
            qa[ks][1] = __float_as_uint(Qg[(size_t)(qr + 8) * HD_ + ks * 8 + qq]);
            qa[ks][2] = __float_as_uint(Qg[(size_t)qr * HD_ + ks * 8 + qq + 4]);
            qa[ks][3] = __float_as_uint(Qg[(size_t)(qr + 8) * HD_ + ks * 8 + qq + 4]);
        }
    }

    const int skey = tid >> 4;          // 0..15 (+16 per it)
    const int sc4  = (tid & 15) * 4;    // 0..60
    auto issue = [&](int s, int kt) {
        const int kbase = kt * 64;
        const unsigned int sb = smem_u32 + s * ATT_STG_B;
        #pragma unroll
        for (int it = 0; it < 4; it++) {
            int key = skey + it * 16;
            cpasync16(sb + (key * KPAD + sc4) * 4, Kg0 + (size_t)(kbase + key) * HD_ + sc4);
            cpasync16(sb + (64 * KPAD + key * VPAD + sc4) * 4,
                      Vg0 + (size_t)(kbase + key) * HD_ + sc4);
        }
        cpcommit();
    };

    float oacc[8][4];
    #pragma unroll
    for (int nt = 0; nt < 8; nt++)
        #pragma unroll
        for (int i = 0; i < 4; i++) oacc[nt][i] = 0.0f;
    float m0 = -1e30f, m1 = -1e30f;
    float l0 = 0.0f,  l1 = 0.0f;

    issue(0, 0);
    issue(1, 1);

    const int srcA = (lane & 28) | (qq >> 1);
    const int srcB = srcA | 2;
    const bool odd = qq & 1;

    for (int kt = 0; kt < NT_; kt++) {
        if (kt < NT_ - 1) { cpwait<1>(); } else { cpwait<0>(); }
        __syncthreads();
        if (kt + 2 < NT_) issue((kt + 2) % 3, kt + 2);

        const float* Ks = (float*)(smem + (kt % 3) * ATT_STG_B);
        const float* Vs = Ks + 64 * KPAD;
        const int kbase = kt * 64;

        // S = Q K^T
        float sacc[8][4];
        #pragma unroll
        for (int nt = 0; nt < 8; nt++) {
            float c[4] = {0.0f, 0.0f, 0.0f, 0.0f};
            const float* kb = Ks + (nt * 8 + qr) * KPAD;
            #pragma unroll
            for (int ks = 0; ks < 8; ks++) {
                unsigned b0 = __float_as_uint(kb[ks * 8 + qq]);
                unsigned b1 = __float_as_uint(kb[ks * 8 + qq + 4]);
                mma_tf32(c, qa[ks], b0, b1);
            }
            sacc[nt][0] = c[0]; sacc[nt][1] = c[1];
            sacc[nt][2] = c[2]; sacc[nt][3] = c[3];
        }

        // online softmax
        float mx0 = -1e30f, mx1 = -1e30f;
        #pragma unroll
        for (int nt = 0; nt < 8; nt++) {
            float ma = Ms[kbase + nt * 8 + 2 * qq];
            float mb = Ms[kbase + nt * 8 + 2 * qq + 1];
            sacc[nt][0] += ma; sacc[nt][1] += mb;
            sacc[nt][2] += ma; sacc[nt][3] += mb;
            mx0 = fmaxf(mx0, fmaxf(sacc[nt][0], sacc[nt][1]));
            mx1 = fmaxf(mx1, fmaxf(sacc[nt][2], sacc[nt][3]));
        }
        mx0 = fmaxf(mx0, __shfl_xor_sync(0xffffffffu, mx0, 1));
        mx0 = fmaxf(mx0, __shfl_xor_sync(0xffffffffu, mx0, 2));
        mx1 = fmaxf(mx1, __shfl_xor_sync(0xffffffffu, mx1, 1));
        mx1 = fmaxf(mx1, __shfl_xor_sync(0xffffffffu, mx1, 2));

        float nm0 = fmaxf(m0, mx0), nm1 = fmaxf(m1, mx1);
        float al0 = __expf(m0 - nm0), al1 = __expf(m1 - nm1);
        float ps0 = 0.0f, ps1 = 0.0f;
        #pragma unroll
        for (int nt = 0; nt < 8; nt++) {
            float p0 = __expf(sacc[nt][0] - nm0);
            float p1 = __expf(sacc[nt][1] - nm0);
            float p2 = __expf(sacc[nt][2] - nm1);
            float p3 = __expf(sacc[nt][3] - nm1);
            ps0 += p0 + p1; ps1 += p2 + p3;
            sacc[nt][0] = p0; sacc[nt][1] = p1;
            sacc[nt][2] = p2; sacc[nt][3] = p3;
        }
        ps0 += __shfl_xor_sync(0xffffffffu, ps0, 1);
        ps0 += __shfl_xor_sync(0xffffffffu, ps0, 2);
        ps1 += __shfl_xor_sync(0xffffffffu, ps1, 1);
        ps1 += __shfl_xor_sync(0xffffffffu, ps1, 2);
        l0 = l0 * al0 + ps0;
        l1 = l1 * al1 + ps1;
        m0 = nm0; m1 = nm1;
        #pragma unroll
        for (int nt = 0; nt < 8; nt++) {
            oacc[nt][0] *= al0; oacc[nt][1] *= al0;
            oacc[nt][2] *= al1; oacc[nt][3] *= al1;
        }

        // O += P V (C->A layout via quad shuffles)
        #pragma unroll
        for (int ks = 0; ks < 8; ks++) {
            float p0 = sacc[ks][0], p1 = sacc[ks][1];
            float p2 = sacc[ks][2], p3 = sacc[ks][3];
            float v0 = __shfl_sync(0xffffffffu, p0, srcA);
            float v1 = __shfl_sync(0xffffffffu, p1, srcA);
            float v2 = __shfl_sync(0xffffffffu, p2, srcA);
            float v3 = __shfl_sync(0xffffffffu, p3, srcA);
            float w0 = __shfl_sync(0xffffffffu, p0, srcB);
            float w1 = __shfl_sync(0xffffffffu, p1, srcB);
            float w2 = __shfl_sync(0xffffffffu, p2, srcB);
            float w3 = __shfl_sync(0xffffffffu, p3, srcB);
            unsigned pa[4];
            pa[0] = __float_as_uint(odd ? v1 : v0);
            pa[1] = __float_as_uint(odd ? v3 : v2);
            pa[2] = __float_as_uint(odd ? w1 : w0);
            pa[3] = __float_as_uint(odd ? w3 : w2);
            const float* vb0 = Vs + (ks * 8 + qq) * VPAD;
            const float* vb1 = Vs + (ks * 8 + qq + 4) * VPAD;
            #pragma unroll
            for (int nt = 0; nt < 8; nt++) {
                unsigned b0 = __float_as_uint(vb0[nt * 8 + qr]);
                unsigned b1 = __float_as_uint(vb1[nt * 8 + qr]);
                mma_tf32(oacc[nt], pa, b0, b1);
            }
        }
        __syncthreads();
    }

    // finalize: divide by l, round to tf32, write [B,H,L,HD]
    {
        float inv0 = (l0 > 0.0f) ? 1.0f / l0 : 0.0f;
        float inv1 = (l1 > 0.0f) ? 1.0f / l1 : 0.0f;
        float* o0 = g_AO + ((size_t)bh * L_ + rowbase + qr) * HD_ + 2 * qq;
        float* o1 = g_AO + ((size_t)bh * L_ + rowbase + qr + 8) * HD_ + 2 * qq;
        #pragma unroll
        for (int nt = 0; nt < 8; nt++) {
            *(float2*)(o0 + nt * 8) = make_float2(
                wmma::__float_to_tf32(oacc[nt][0] * inv0),
                wmma::__float_to_tf32(oacc[nt][1] * inv0));
            *(float2*)(o1 + nt * 8) = make_float2(
                wmma::__float_to_tf32(oacc[nt][2] * inv1),
                wmma::__float_to_tf32(oacc[nt][3] * inv1));
        }
    }
}

// ---------------------------------------------------------------------------
// Output projection: out = AO_merged @ Wo^T + bo. 3-stage cp.async pipeline.
// ---------------------------------------------------------------------------
__global__ __launch_bounds__(256) void oproj_kernel(
    const float* __restrict__ bo, float* __restrict__ out)
{
    extern __shared__ char smem[];
    const unsigned int smem_u32 = (unsigned int)__cvta_generic_to_shared(smem);
    float* Cs = (float*)smem;

    const float* W = g_Wt + (size_t)3 * (D_ * D_);

    const int m0 = blockIdx.x * 128;
    const int n0 = blockIdx.y * 128;
    const int tid = threadIdx.x;
    const int warp = tid >> 5;
    const int wm = (warp >> 2) * 64;
    const int wn = (warp & 3) * 32;

    const int lr  = tid >> 3;
    const int lc4 = (tid & 7) * 4;

    wmma::fragment<wmma::accumulator, 16, 16, 8, float> acc[4][2];
    #pragma unroll
    for (int i = 0; i < 4; i++)
        #pragma unroll
        for (int j = 0; j < 2; j++) wmma::fill_fragment(acc[i][j], 0.0f);

    auto issue = [&](int s, int kt) {
        const int k0 = kt * 32;
        const int head = k0 >> 6;
        const int koff = k0 & (HD_ - 1);
        const unsigned int sb = smem_u32 + s * STG_B;
        #pragma unroll
        for (int it = 0; it < 4; it++) {
            int r = lr + it * 32;
            int m = m0 + r;
            int b = m >> 11, l = m & (L_ - 1);
            cpasync16(sb + (r * 36 + lc4) * 4,
                      g_AO + (((size_t)(b * H_ + head)) * L_ + l) * HD_ + koff + lc4);
            cpasync16(sb + (STG_F + r * 36 + lc4) * 4, W + (size_t)(n0 + r) * D_ + k0 + lc4);
        }
        cpcommit();
    };

    issue(0, 0);
    issue(1, 1);

    for (int kt = 0; kt < NKP; kt++) {
        if (kt < NKP - 1) { cpwait<1>(); } else { cpwait<0>(); }
        __syncthreads();
        if (kt + 2 < NKP) issue((kt + 2) % 3, kt + 2);

        const float* As = (float*)(smem + (kt % 3) * STG_B);
        const float* Bs = As + STG_F;
        #pragma unroll
        for (int kk = 0; kk < 4; kk++) {
            wmma::fragment<wmma::matrix_a, 16, 16, 8, wmma::precision::tf32, wmma::row_major> af[4];
            wmma::fragment<wmma::matrix_b, 16, 16, 8, wmma::precision::tf32, wmma::col_major> bf[2];
            #pragma unroll
            for (int i = 0; i < 4; i++)
                wmma::load_matrix_sync(af[i], As + (wm + i * 16) * 36 + kk * 8, 36);
            #pragma unroll
            for (int j = 0; j < 2; j++)
                wmma::load_matrix_sync(bf[j], Bs + (wn + j * 16) * 36 + kk * 8, 36);
            #pragma unroll
            for (int i = 0; i < 4; i++)
                #pragma unroll
                for (int j = 0; j < 2; j++)
                    wmma::mma_sync(acc[i][j], af[i], bf[j], acc[i][j]);
        }
        __syncthreads();
    }

    #pragma unroll
    for (int i = 0; i < 4; i++)
        #pragma unroll
        for (int j = 0; j < 2; j++)
            wmma::store_matrix_sync(Cs + (wm + i * 16) * 132 + wn + j * 16, acc[i][j],
                                    132, wmma::mem_row_major);
    __syncthreads();

    #pragma unroll 8
    for (int it = 0; it < 64; it++) {
        int idx = tid + it * 256;
        int r = idx >> 7;
        int c = idx & 127;
        int m = m0 + r, n = n0 + c;
        out[(size_t)m * D_ + n] = Cs[r * 132 + c] + bo[n];
    }
}

// ---------------------------------------------------------------------------
extern "C" void kernel_launch(void* const* d_in, const int* in_sizes, int n_in,
                              void* d_out, int out_size)
{
    const float* q    = (const float*)d_in[0];
    const float* k    = (const float*)d_in[1];
    const float* v    = (const float*)d_in[2];
    const unsigned char* mask = (const unsigned char*)d_in[3];
    const float* Wq   = (const float*)d_in[4];
    const float* bq   = (const float*)d_in[5];
    const float* Wk   = (const float*)d_in[6];
    const float* bk   = (const float*)d_in[7];
    const float* Wv   = (const float*)d_in[8];
    const float* bv   = (const float*)d_in[9];
    const float* Wo   = (const float*)d_in[10];
    const float* bo   = (const float*)d_in[11];
    float* out        = (float*)d_out;

    const int projSmem = 3 * STG_B;                    // 110592
    const int attnSmem = 3 * ATT_STG_B + L_ * 4;       // 107520 + 8192 = 115712

    cudaFuncSetAttribute(proj_kernel,  cudaFuncAttributeMaxDynamicSharedMemorySize, projSmem);
    cudaFuncSetAttribute(attn_kernel,  cudaFuncAttributeMaxDynamicSharedMemorySize, attnSmem);
    cudaFuncSetAttribute(oproj_kernel, cudaFuncAttributeMaxDynamicSharedMemorySize, projSmem);

    prep_kernel<<<(4 * D_ * D_ + 3 * M_ * D_) / (4 * 256), 256>>>(q, k, v, Wq, Wk, Wv, Wo);

    dim3 gProj(M_ / 128, D_ / 128, 3);
    proj_kernel<<<gProj, 256, projSmem>>>(bq, bk, bv);

    dim3 gAttn(L_ / 128, B_ * H_);
    attn_kernel<<<gAttn, 256, attnSmem>>>(mask);

    dim3 gOut(M_ / 128, D_ / 128);
    oproj_kernel<<<gOut, 256, projSmem>>>(bo, out);
}

// round 7
// speedup vs baseline: 2.4742x; 1.0915x over previous
#include <cuda_runtime.h>
#include <cuda_bf16.h>
#include <mma.h>
#include <cstdint>

using namespace nvcuda;

#define B_  2
#define L_  2048
#define D_  1024
#define H_  16
#define HD_ 64
#define M_  (B_ * L_)   // 4096

// Scratch (static __device__ arrays: allocation-free per harness rules)
__device__ float g_Qp[B_ * H_ * L_ * HD_];
__device__ float g_Kp[B_ * H_ * L_ * HD_];
__device__ float g_Vp[B_ * H_ * L_ * HD_];
__device__ float g_AO[B_ * H_ * L_ * HD_];
__device__ float g_Wt[4 * D_ * D_];          // tf32-rounded Wq,Wk,Wv,Wo
__device__ float g_Xt[3 * M_ * D_];          // tf32-rounded q,k,v

// ---------------------------------------------------------------------------
// cp.async helpers
// ---------------------------------------------------------------------------
__device__ __forceinline__ void cpasync16(unsigned int dst, const float* src) {
    asm volatile("cp.async.cg.shared.global [%0], [%1], 16;" :: "r"(dst), "l"(src));
}
__device__ __forceinline__ void cpcommit() {
    asm volatile("cp.async.commit_group;");
}
template<int N> __device__ __forceinline__ void cpwait() {
    asm volatile("cp.async.wait_group %0;" :: "n"(N));
}

// ---------------------------------------------------------------------------
// Pre-pass: round weights + activations to tf32 (RN) once.
// ---------------------------------------------------------------------------
__global__ __launch_bounds__(256) void prep_kernel(
    const float* __restrict__ q, const float* __restrict__ k, const float* __restrict__ v,
    const float* __restrict__ Wq, const float* __restrict__ Wk,
    const float* __restrict__ Wv, const float* __restrict__ Wo)
{
    const int idx4 = blockIdx.x * 256 + threadIdx.x;
    const int e = idx4 * 4;
    const float* src;
    float* dst;
    if (e < 4 * D_ * D_) {
        int wsel = e >> 20;
        int off  = e & (D_ * D_ - 1);
        src = ((wsel == 0) ? Wq : (wsel == 1) ? Wk : (wsel == 2) ? Wv : Wo) + off;
        dst = g_Wt + e;
    } else {
        int xe   = e - 4 * D_ * D_;
        int xsel = xe >> 22;
        int off  = xe & (M_ * D_ - 1);
        src = ((xsel == 0) ? q : (xsel == 1) ? k : v) + off;
        dst = g_Xt + xe;
    }
    float4 val = *(const float4*)src;
    val.x = wmma::__float_to_tf32(val.x);
    val.y = wmma::__float_to_tf32(val.y);
    val.z = wmma::__float_to_tf32(val.z);
    val.w = wmma::__float_to_tf32(val.w);
    *(float4*)dst = val;
}

// ---------------------------------------------------------------------------
// Fused Q/K/V projection: Y = X @ W^T + b, head-split [B,H,L,HD].
// 2-stage cp.async pipeline, 2 CTAs/SM.
// ---------------------------------------------------------------------------
#define NKP (D_ / 32)          // 32 k-iterations
#define STG_F (128 * 36)       // floats per operand tile
#define STG_B (2 * STG_F * 4)  // bytes per stage (A + B) = 36864

__global__ __launch_bounds__(256, 2) void proj_kernel(
    const float* __restrict__ bq, const float* __restrict__ bk, const float* __restrict__ bv)
{
    extern __shared__ char smem[];
    const unsigned int smem_u32 = (unsigned int)__cvta_generic_to_shared(smem);
    float* Cs = (float*)smem;   // epilogue reuse [128][132]

    const int z = blockIdx.z;
    const float* X    = g_Xt + (size_t)z * (M_ * D_);
    const float* W    = g_Wt + (size_t)z * (D_ * D_);
    const float* bias = (z == 0) ? bq : (z == 1) ? bk : bv;
    float* outp       = (z == 0) ? g_Qp : (z == 1) ? g_Kp : g_Vp;

    const int m0 = blockIdx.x * 128;
    const int n0 = blockIdx.y * 128;
    const int tid = threadIdx.x;
    const int warp = tid >> 5;
    const int wm = (warp >> 2) * 64;
    const int wn = (warp & 3) * 32;

    const int lr  = tid >> 3;
    const int lc4 = (tid & 7) * 4;

    wmma::fragment<wmma::accumulator, 16, 16, 8, float> acc[4][2];
    #pragma unroll
    for (int i = 0; i < 4; i++)
        #pragma unroll
        for (int j = 0; j < 2; j++) wmma::fill_fragment(acc[i][j], 0.0f);

    auto issue = [&](int s, int kt) {
        const int k0 = kt * 32;
        const unsigned int sb = smem_u32 + s * STG_B;
        #pragma unroll
        for (int it = 0; it < 4; it++) {
            int r = lr + it * 32;
            cpasync16(sb + (r * 36 + lc4) * 4, X + (size_t)(m0 + r) * D_ + k0 + lc4);
            cpasync16(sb + (STG_F + r * 36 + lc4) * 4, W + (size_t)(n0 + r) * D_ + k0 + lc4);
        }
        cpcommit();
    };

    issue(0, 0);
    issue(1, 1);

    for (int kt = 0; kt < NKP; kt++) {
        if (kt < NKP - 1) { cpwait<1>(); } else { cpwait<0>(); }
        __syncthreads();

        const float* As = (float*)(smem + (kt & 1) * STG_B);
        const float* Bs = As + STG_F;
        #pragma unroll
        for (int kk = 0; kk < 4; kk++) {
            wmma::fragment<wmma::matrix_a, 16, 16, 8, wmma::precision::tf32, wmma::row_major> af[4];
            wmma::fragment<wmma::matrix_b, 16, 16, 8, wmma::precision::tf32, wmma::col_major> bf[2];
            #pragma unroll
            for (int i = 0; i < 4; i++)
                wmma::load_matrix_sync(af[i], As + (wm + i * 16) * 36 + kk * 8, 36);
            #pragma unroll
            for (int j = 0; j < 2; j++)
                wmma::load_matrix_sync(bf[j], Bs + (wn + j * 16) * 36 + kk * 8, 36);
            #pragma unroll
            for (int i = 0; i < 4; i++)
                #pragma unroll
                for (int j = 0; j < 2; j++)
                    wmma::mma_sync(acc[i][j], af[i], bf[j], acc[i][j]);
        }
        __syncthreads();
        if (kt + 2 < NKP) issue(kt & 1, kt + 2);
    }
    __syncthreads();

    #pragma unroll
    for (int i = 0; i < 4; i++)
        #pragma unroll
        for (int j = 0; j < 2; j++)
            wmma::store_matrix_sync(Cs + (wm + i * 16) * 132 + wn + j * 16, acc[i][j],
                                    132, wmma::mem_row_major);
    __syncthreads();

    const float qscale = (z == 0) ? 0.125f : 1.0f;
    #pragma unroll 8
    for (int it = 0; it < 64; it++) {
        int idx = tid + it * 256;
        int r = idx >> 7;
        int c = idx & 127;
        int m = m0 + r, n = n0 + c;
        int b = m >> 11, l = m & (L_ - 1);
        int h = n >> 6, hd = n & (HD_ - 1);
        float val = wmma::__float_to_tf32(Cs[r * 132 + c] + bias[n]) * qscale;
        outp[(((size_t)(b * H_ + h)) * L_ + l) * HD_ + hd] = val;
    }
}

// ---------------------------------------------------------------------------
// Flash attention, register-resident, 2-stage cp.async K/V pipeline,
// 2 CTAs/SM. CTA = 128 queries x one (b,h), 8 warps.
// ---------------------------------------------------------------------------
__device__ __forceinline__ void mma_tf32(float c[4], const unsigned a[4],
                                         unsigned b0, unsigned b1)
{
    asm volatile(
        "mma.sync.aligned.m16n8k8.row.col.f32.tf32.tf32.f32 "
        "{%0,%1,%2,%3}, {%4,%5,%6,%7}, {%8,%9}, {%0,%1,%2,%3};"
        : "+f"(c[0]), "+f"(c[1]), "+f"(c[2]), "+f"(c[3])
        : "r"(a[0]), "r"(a[1]), "r"(a[2]), "r"(a[3]), "r"(b0), "r"(b1));
}

#define KPAD 68
#define VPAD 72
#define ATT_STG_F (64 * KPAD + 64 * VPAD)
#define ATT_STG_B (ATT_STG_F * 4)            // 35840
#define NT_ (L_ / 64)

__global__ __launch_bounds__(256, 2) void attn_kernel(const unsigned char* __restrict__ mask)
{
    extern __shared__ char smem[];
    const unsigned int smem_u32 = (unsigned int)__cvta_generic_to_shared(smem);
    float* Ms = (float*)(smem + 2 * ATT_STG_B);   // [2048] mask adds

    const int q0   = blockIdx.x * 128;
    const int bh   = blockIdx.y;
    const int b    = bh >> 4;
    const int tid  = threadIdx.x;
    const int warp = tid >> 5;
    const int lane = tid & 31;
    const int qr   = lane >> 2;
    const int qq   = lane & 3;
    const int rowbase = q0 + warp * 16;

    const float* Kg0 = g_Kp + (size_t)bh * L_ * HD_;
    const float* Vg0 = g_Vp + (size_t)bh * L_ * HD_;

    for (int i = tid; i < L_; i += 256)
        Ms[i] = mask[b * L_ + i] ? -1e30f : 0.0f;

    unsigned qa[8][4];
    {
        const float* Qg = g_Qp + ((size_t)bh * L_ + rowbase) * HD_;
        #pragma unroll
        for (int ks = 0; ks < 8; ks++) {
            qa[ks][0] = __float_as_uint(Qg[(size_t)qr * HD_ + ks * 8 + qq]);
            qa[ks][1] = __float_as_uint(Qg[(size_t)(qr + 8) * HD_ + ks * 8 + qq]);
            qa[ks][2] = __float_as_uint(Qg[(size_t)qr * HD_ + ks * 8 + qq + 4]);
            qa[ks][3] = __float_as_uint(Qg[(size_t)(qr + 8) * HD_ + ks * 8 + qq + 4]);
        }
    }

    const int skey = tid >> 4;
    const int sc4  = (tid & 15) * 4;
    auto issue = [&](int s, int kt) {
        const int kbase = kt * 64;
        const unsigned int sb = smem_u32 + s * ATT_STG_B;
        #pragma unroll
        for (int it = 0; it < 4; it++) {
            int key = skey + it * 16;
            cpasync16(sb + (key * KPAD + sc4) * 4, Kg0 + (size_t)(kbase + key) * HD_ + sc4);
            cpasync16(sb + (64 * KPAD + key * VPAD + sc4) * 4,
                      Vg0 + (size_t)(kbase + key) * HD_ + sc4);
        }
        cpcommit();
    };

    float oacc[8][4];
    #pragma unroll
    for (int nt = 0; nt < 8; nt++)
        #pragma unroll
        for (int i = 0; i < 4; i++) oacc[nt][i] = 0.0f;
    float m0 = -1e30f, m1 = -1e30f;
    float l0 = 0.0f,  l1 = 0.0f;

    issue(0, 0);
    issue(1, 1);

    const int srcA = (lane & 28) | (qq >> 1);
    const int srcB = srcA | 2;
    const bool odd = qq & 1;

    for (int kt = 0; kt < NT_; kt++) {
        if (kt < NT_ - 1) { cpwait<1>(); } else { cpwait<0>(); }
        __syncthreads();

        const float* Ks = (float*)(smem + (kt & 1) * ATT_STG_B);
        const float* Vs = Ks + 64 * KPAD;
        const int kbase = kt * 64;

        // S = Q K^T
        float sacc[8][4];
        #pragma unroll
        for (int nt = 0; nt < 8; nt++) {
            float c[4] = {0.0f, 0.0f, 0.0f, 0.0f};
            const float* kb = Ks + (nt * 8 + qr) * KPAD;
            #pragma unroll
            for (int ks = 0; ks < 8; ks++) {
                unsigned b0 = __float_as_uint(kb[ks * 8 + qq]);
                unsigned b1 = __float_as_uint(kb[ks * 8 + qq + 4]);
                mma_tf32(c, qa[ks], b0, b1);
            }
            sacc[nt][0] = c[0]; sacc[nt][1] = c[1];
            sacc[nt][2] = c[2]; sacc[nt][3] = c[3];
        }

        // online softmax
        float mx0 = -1e30f, mx1 = -1e30f;
        #pragma unroll
        for (int nt = 0; nt < 8; nt++) {
            float ma = Ms[kbase + nt * 8 + 2 * qq];
            float mb = Ms[kbase + nt * 8 + 2 * qq + 1];
            sacc[nt][0] += ma; sacc[nt][1] += mb;
            sacc[nt][2] += ma; sacc[nt][3] += mb;
            mx0 = fmaxf(mx0, fmaxf(sacc[nt][0], sacc[nt][1]));
            mx1 = fmaxf(mx1, fmaxf(sacc[nt][2], sacc[nt][3]));
        }
        mx0 = fmaxf(mx0, __shfl_xor_sync(0xffffffffu, mx0, 1));
        mx0 = fmaxf(mx0, __shfl_xor_sync(0xffffffffu, mx0, 2));
        mx1 = fmaxf(mx1, __shfl_xor_sync(0xffffffffu, mx1, 1));
        mx1 = fmaxf(mx1, __shfl_xor_sync(0xffffffffu, mx1, 2));

        float nm0 = fmaxf(m0, mx0), nm1 = fmaxf(m1, mx1);
        float al0 = __expf(m0 - nm0), al1 = __expf(m1 - nm1);
        float ps0 = 0.0f, ps1 = 0.0f;
        #pragma unroll
        for (int nt = 0; nt < 8; nt++) {
            float p0 = __expf(sacc[nt][0] - nm0);
            float p1 = __expf(sacc[nt][1] - nm0);
            float p2 = __expf(sacc[nt][2] - nm1);
            float p3 = __expf(sacc[nt][3] - nm1);
            ps0 += p0 + p1; ps1 += p2 + p3;
            sacc[nt][0] = p0; sacc[nt][1] = p1;
            sacc[nt][2] = p2; sacc[nt][3] = p3;
        }
        ps0 += __shfl_xor_sync(0xffffffffu, ps0, 1);
        ps0 += __shfl_xor_sync(0xffffffffu, ps0, 2);
        ps1 += __shfl_xor_sync(0xffffffffu, ps1, 1);
        ps1 += __shfl_xor_sync(0xffffffffu, ps1, 2);
        l0 = l0 * al0 + ps0;
        l1 = l1 * al1 + ps1;
        m0 = nm0; m1 = nm1;
        #pragma unroll
        for (int nt = 0; nt < 8; nt++) {
            oacc[nt][0] *= al0; oacc[nt][1] *= al0;
            oacc[nt][2] *= al1; oacc[nt][3] *= al1;
        }

        // O += P V
        #pragma unroll
        for (int ks = 0; ks < 8; ks++) {
            float p0 = sacc[ks][0], p1 = sacc[ks][1];
            float p2 = sacc[ks][2], p3 = sacc[ks][3];
            float v0 = __shfl_sync(0xffffffffu, p0, srcA);
            float v1 = __shfl_sync(0xffffffffu, p1, srcA);
            float v2 = __shfl_sync(0xffffffffu, p2, srcA);
            float v3 = __shfl_sync(0xffffffffu, p3, srcA);
            float w0 = __shfl_sync(0xffffffffu, p0, srcB);
            float w1 = __shfl_sync(0xffffffffu, p1, srcB);
            float w2 = __shfl_sync(0xffffffffu, p2, srcB);
            float w3 = __shfl_sync(0xffffffffu, p3, srcB);
            unsigned pa[4];
            pa[0] = __float_as_uint(odd ? v1 : v0);
            pa[1] = __float_as_uint(odd ? v3 : v2);
            pa[2] = __float_as_uint(odd ? w1 : w0);
            pa[3] = __float_as_uint(odd ? w3 : w2);
            const float* vb0 = Vs + (ks * 8 + qq) * VPAD;
            const float* vb1 = Vs + (ks * 8 + qq + 4) * VPAD;
            #pragma unroll
            for (int nt = 0; nt < 8; nt++) {
                unsigned b0 = __float_as_uint(vb0[nt * 8 + qr]);
                unsigned b1 = __float_as_uint(vb1[nt * 8 + qr]);
                mma_tf32(oacc[nt], pa, b0, b1);
            }
        }
        __syncthreads();
        if (kt + 2 < NT_) issue(kt & 1, kt + 2);
    }

    // finalize
    {
        float inv0 = (l0 > 0.0f) ? 1.0f / l0 : 0.0f;
        float inv1 = (l1 > 0.0f) ? 1.0f / l1 : 0.0f;
        float* o0 = g_AO + ((size_t)bh * L_ + rowbase + qr) * HD_ + 2 * qq;
        float* o1 = g_AO + ((size_t)bh * L_ + rowbase + qr + 8) * HD_ + 2 * qq;
        #pragma unroll
        for (int nt = 0; nt < 8; nt++) {
            *(float2*)(o0 + nt * 8) = make_float2(
                wmma::__float_to_tf32(oacc[nt][0] * inv0),
                wmma::__float_to_tf32(oacc[nt][1] * inv0));
            *(float2*)(o1 + nt * 8) = make_float2(
                wmma::__float_to_tf32(oacc[nt][2] * inv1),
                wmma::__float_to_tf32(oacc[nt][3] * inv1));
        }
    }
}

// ---------------------------------------------------------------------------
// Output projection: out = AO_merged @ Wo^T + bo. 2-stage cp.async, 2 CTAs/SM.
// ---------------------------------------------------------------------------
__global__ __launch_bounds__(256, 2) void oproj_kernel(
    const float* __restrict__ bo, float* __restrict__ out)
{
    extern __shared__ char smem[];
    const unsigned int smem_u32 = (unsigned int)__cvta_generic_to_shared(smem);
    float* Cs = (float*)smem;

    const float* W = g_Wt + (size_t)3 * (D_ * D_);

    const int m0 = blockIdx.x * 128;
    const int n0 = blockIdx.y * 128;
    const int tid = threadIdx.x;
    const int warp = tid >> 5;
    const int wm = (warp >> 2) * 64;
    const int wn = (warp & 3) * 32;

    const int lr  = tid >> 3;
    const int lc4 = (tid & 7) * 4;

    wmma::fragment<wmma::accumulator, 16, 16, 8, float> acc[4][2];
    #pragma unroll
    for (int i = 0; i < 4; i++)
        #pragma unroll
        for (int j = 0; j < 2; j++) wmma::fill_fragment(acc[i][j], 0.0f);

    auto issue = [&](int s, int kt) {
        const int k0 = kt * 32;
        const int head = k0 >> 6;
        const int koff = k0 & (HD_ - 1);
        const unsigned int sb = smem_u32 + s * STG_B;
        #pragma unroll
        for (int it = 0; it < 4; it++) {
            int r = lr + it * 32;
            int m = m0 + r;
            int b = m >> 11, l = m & (L_ - 1);
            cpasync16(sb + (r * 36 + lc4) * 4,
                      g_AO + (((size_t)(b * H_ + head)) * L_ + l) * HD_ + koff + lc4);
            cpasync16(sb + (STG_F + r * 36 + lc4) * 4, W + (size_t)(n0 + r) * D_ + k0 + lc4);
        }
        cpcommit();
    };

    issue(0, 0);
    issue(1, 1);

    for (int kt = 0; kt < NKP; kt++) {
        if (kt < NKP - 1) { cpwait<1>(); } else { cpwait<0>(); }
        __syncthreads();

        const float* As = (float*)(smem + (kt & 1) * STG_B);
        const float* Bs = As + STG_F;
        #pragma unroll
        for (int kk = 0; kk < 4; kk++) {
            wmma::fragment<wmma::matrix_a, 16, 16, 8, wmma::precision::tf32, wmma::row_major> af[4];
            wmma::fragment<wmma::matrix_b, 16, 16, 8, wmma::precision::tf32, wmma::col_major> bf[2];
            #pragma unroll
            for (int i = 0; i < 4; i++)
                wmma::load_matrix_sync(af[i], As + (wm + i * 16) * 36 + kk * 8, 36);
            #pragma unroll
            for (int j = 0; j < 2; j++)
                wmma::load_matrix_sync(bf[j], Bs + (wn + j * 16) * 36 + kk * 8, 36);
            #pragma unroll
            for (int i = 0; i < 4; i++)
                #pragma unroll
                for (int j = 0; j < 2; j++)
                    wmma::mma_sync(acc[i][j], af[i], bf[j], acc[i][j]);
        }
        __syncthreads();
        if (kt + 2 < NKP) issue(kt & 1, kt + 2);
    }
    __syncthreads();

    #pragma unroll
    for (int i = 0; i < 4; i++)
        #pragma unroll
        for (int j = 0; j < 2; j++)
            wmma::store_matrix_sync(Cs + (wm + i * 16) * 132 + wn + j * 16, acc[i][j],
                                    132, wmma::mem_row_major);
    __syncthreads();

    #pragma unroll 8
    for (int it = 0; it < 64; it++) {
        int idx = tid + it * 256;
        int r = idx >> 7;
        int c = idx & 127;
        int m = m0 + r, n = n0 + c;
        out[(size_t)m * D_ + n] = Cs[r * 132 + c] + bo[n];
    }
}

// ---------------------------------------------------------------------------
extern "C" void kernel_launch(void* const* d_in, const int* in_sizes, int n_in,
                              void* d_out, int out_size)
{
    const float* q    = (const float*)d_in[0];
    const float* k    = (const float*)d_in[1];
    const float* v    = (const float*)d_in[2];
    const unsigned char* mask = (const unsigned char*)d_in[3];
    const float* Wq   = (const float*)d_in[4];
    const float* bq   = (const float*)d_in[5];
    const float* Wk   = (const float*)d_in[6];
    const float* bk   = (const float*)d_in[7];
    const float* Wv   = (const float*)d_in[8];
    const float* bv   = (const float*)d_in[9];
    const float* Wo   = (const float*)d_in[10];
    const float* bo   = (const float*)d_in[11];
    float* out        = (float*)d_out;

    const int projSmem = 2 * STG_B;                    // 73728
    const int attnSmem = 2 * ATT_STG_B + L_ * 4;       // 71680 + 8192 = 79872

    cudaFuncSetAttribute(proj_kernel,  cudaFuncAttributeMaxDynamicSharedMemorySize, projSmem);
    cudaFuncSetAttribute(attn_kernel,  cudaFuncAttributeMaxDynamicSharedMemorySize, attnSmem);
    cudaFuncSetAttribute(oproj_kernel, cudaFuncAttributeMaxDynamicSharedMemorySize, projSmem);

    prep_kernel<<<(4 * D_ * D_ + 3 * M_ * D_) / (4 * 256), 256>>>(q, k, v, Wq, Wk, Wv, Wo);

    dim3 gProj(M_ / 128, D_ / 128, 3);
    proj_kernel<<<gProj, 256, projSmem>>>(bq, bk, bv);

    dim3 gAttn(L_ / 128, B_ * H_);
    attn_kernel<<<gAttn, 256, attnSmem>>>(mask);

    dim3 gOut(M_ / 128, D_ / 128);
    oproj_kernel<<<gOut, 256, projSmem>>>(bo, out);
}

// round 8
// speedup vs baseline: 4.0063x; 1.6192x over previous
#include <cuda_runtime.h>
#include <cuda_bf16.h>
#include <mma.h>
#include <cstdint>

using namespace nvcuda;

#define B_  2
#define L_  2048
#define D_  1024
#define H_  16
#define HD_ 64
#define M_  (B_ * L_)   // 4096

// Scratch (static __device__ arrays: allocation-free per harness rules)
// g_Qp/g_Kp: [bh][l][hd'] with hd' k-permuted within 8-groups.
// g_Vp: [bh][l/8 group][pair(=j&3)][hd][slot(=j>>2)] pair-packed.
// g_AO: [bh][l][hd'] hd-permuted (oproj A operand).
// g_Wt/g_Xt: rows with k-dim permuted within 8-groups.
__device__ float g_Qp[B_ * H_ * L_ * HD_];
__device__ float g_Kp[B_ * H_ * L_ * HD_];
__device__ float g_Vp[B_ * H_ * L_ * HD_];
__device__ float g_AO[B_ * H_ * L_ * HD_];
__device__ float g_Wt[4 * D_ * D_];
__device__ float g_Xt[3 * M_ * D_];

// k-permutation within an 8-group: [0,4,1,5,2,6,3,7] -> pos(j) = (j&3)*2 + (j>>2)
__device__ __forceinline__ int kperm(int j) { return ((j & 3) << 1) | (j >> 2); }

// ---------------------------------------------------------------------------
// cp.async helpers
// ---------------------------------------------------------------------------
__device__ __forceinline__ void cpasync16(unsigned int dst, const float* src) {
    asm volatile("cp.async.cg.shared.global [%0], [%1], 16;" :: "r"(dst), "l"(src));
}
__device__ __forceinline__ void cpcommit() {
    asm volatile("cp.async.commit_group;");
}
template<int N> __device__ __forceinline__ void cpwait() {
    asm volatile("cp.async.wait_group %0;" :: "n"(N));
}

__device__ __forceinline__ void mma_tf32(float c[4], const unsigned a[4],
                                         unsigned b0, unsigned b1)
{
    asm volatile(
        "mma.sync.aligned.m16n8k8.row.col.f32.tf32.tf32.f32 "
        "{%0,%1,%2,%3}, {%4,%5,%6,%7}, {%8,%9}, {%0,%1,%2,%3};"
        : "+f"(c[0]), "+f"(c[1]), "+f"(c[2]), "+f"(c[3])
        : "r"(a[0]), "r"(a[1]), "r"(a[2]), "r"(a[3]), "r"(b0), "r"(b1));
}

// ---------------------------------------------------------------------------
// Pre-pass: tf32-round weights + activations, store k-permuted.
// ---------------------------------------------------------------------------
__global__ __launch_bounds__(256) void prep_kernel(
    const float* __restrict__ q, const float* __restrict__ k, const float* __restrict__ v,
    const float* __restrict__ Wq, const float* __restrict__ Wk,
    const float* __restrict__ Wv, const float* __restrict__ Wo)
{
    const int idx4 = blockIdx.x * 256 + threadIdx.x;
    const int e = idx4 * 4;
    const float* src;
    float* dst;
    if (e < 4 * D_ * D_) {
        int wsel = e >> 20;
        int off  = e & (D_ * D_ - 1);
        src = ((wsel == 0) ? Wq : (wsel == 1) ? Wk : (wsel == 2) ? Wv : Wo) + off;
        dst = g_Wt + (e & ~(D_ * D_ - 1));   // base of this matrix
        dst += 0;
        // element offset handled below with permute
        float4 val = *(const float4*)src;
        float vv[4] = {val.x, val.y, val.z, val.w};
        #pragma unroll
        for (int i = 0; i < 4; i++) {
            int fe = off + i;
            int pos = (fe & ~7) | kperm(fe & 7);
            g_Wt[(size_t)wsel * (D_ * D_) + pos] = wmma::__float_to_tf32(vv[i]);
        }
    } else {
        int xe   = e - 4 * D_ * D_;
        int xsel = xe >> 22;
        int off  = xe & (M_ * D_ - 1);
        src = ((xsel == 0) ? q : (xsel == 1) ? k : v) + off;
        float4 val = *(const float4*)src;
        float vv[4] = {val.x, val.y, val.z, val.w};
        #pragma unroll
        for (int i = 0; i < 4; i++) {
            int fe = off + i;
            int pos = (fe & ~7) | kperm(fe & 7);
            g_Xt[(size_t)xsel * (M_ * D_) + pos] = wmma::__float_to_tf32(vv[i]);
        }
    }
}

// ---------------------------------------------------------------------------
// tf32 GEMM core, raw mma + float2 fragment loads. CTA tile 128x128,
// warp tile 64x32 (2x4 warp grid), 2-stage cp.async, 2 CTAs/SM.
// Operands A,B stored K-major with k-permuted 8-groups; PAD 40 floats.
// ---------------------------------------------------------------------------
#define NKP   (D_ / 32)
#define GPAD  40
#define GSTG_F (128 * GPAD)           // floats per operand tile
#define GSTG_B (2 * GSTG_F * 4)       // 40960 bytes per stage

// GEMM mainloop; leaves result in c[4][4][4]. AGet/BGet give gmem pointers
// for (row 0..127, kt, chunk 0..7) -> 16B-aligned float*.
template<typename AF, typename BF>
__device__ __forceinline__ void gemm_core(char* smem, AF aget, BF bget,
                                          float c[4][4][4])
{
    const unsigned int smem_u32 = (unsigned int)__cvta_generic_to_shared(smem);
    const int tid  = threadIdx.x;
    const int warp = tid >> 5;
    const int lane = tid & 31;
    const int qr   = lane >> 2;
    const int qq   = lane & 3;
    const int wm = (warp >> 2) * 64;
    const int wn = (warp & 3) * 32;
    const int lr  = tid >> 3;
    const int lc4 = (tid & 7) * 4;

    #pragma unroll
    for (int i = 0; i < 4; i++)
        #pragma unroll
        for (int j = 0; j < 4; j++)
            #pragma unroll
            for (int r = 0; r < 4; r++) c[i][j][r] = 0.0f;

    auto issue = [&](int s, int kt) {
        const unsigned int sb = smem_u32 + s * GSTG_B;
        #pragma unroll
        for (int it = 0; it < 4; it++) {
            int r = lr + it * 32;
            cpasync16(sb + (r * GPAD + lc4) * 4,            aget(r, kt, lc4 >> 2));
            cpasync16(sb + (GSTG_F + r * GPAD + lc4) * 4,   bget(r, kt, lc4 >> 2));
        }
        cpcommit();
    };

    issue(0, 0);
    issue(1, 1);

    for (int kt = 0; kt < NKP; kt++) {
        if (kt < NKP - 1) { cpwait<1>(); } else { cpwait<0>(); }
        __syncthreads();

        const float* As = (const float*)(smem + (kt & 1) * GSTG_B);
        const float* Bs = As + GSTG_F;

        #pragma unroll
        for (int kk = 0; kk < 4; kk++) {
            float2 a0[4], a1[4], bv[4];
            #pragma unroll
            for (int i = 0; i < 4; i++) {
                a0[i] = *(const float2*)(As + (wm + 16 * i + qr) * GPAD + kk * 8 + 2 * qq);
                a1[i] = *(const float2*)(As + (wm + 16 * i + qr + 8) * GPAD + kk * 8 + 2 * qq);
            }
            #pragma unroll
            for (int j = 0; j < 4; j++)
                bv[j] = *(const float2*)(Bs + (wn + 8 * j + qr) * GPAD + kk * 8 + 2 * qq);
            #pragma unroll
            for (int i = 0; i < 4; i++) {
                unsigned af[4] = { __float_as_uint(a0[i].x), __float_as_uint(a1[i].x),
                                   __float_as_uint(a0[i].y), __float_as_uint(a1[i].y) };
                #pragma unroll
                for (int j = 0; j < 4; j++)
                    mma_tf32(c[i][j], af, __float_as_uint(bv[j].x), __float_as_uint(bv[j].y));
            }
        }
        __syncthreads();
        if (kt + 2 < NKP) issue(kt & 1, kt + 2);
    }

    // store fragments to Cs [128][132]
    float* Cs = (float*)smem;
    __syncthreads();
    #pragma unroll
    for (int i = 0; i < 4; i++)
        #pragma unroll
        for (int j = 0; j < 4; j++) {
            *(float2*)(Cs + (wm + 16 * i + qr) * 132 + wn + 8 * j + 2 * qq) =
                make_float2(c[i][j][0], c[i][j][1]);
            *(float2*)(Cs + (wm + 16 * i + qr + 8) * 132 + wn + 8 * j + 2 * qq) =
                make_float2(c[i][j][2], c[i][j][3]);
        }
    __syncthreads();
}

// ---------------------------------------------------------------------------
// Q/K/V projection. Outputs: Q/K hd-permuted (Q scaled 1/8), V pair-packed.
// ---------------------------------------------------------------------------
__global__ __launch_bounds__(256, 2) void proj_kernel(
    const float* __restrict__ bq, const float* __restrict__ bk, const float* __restrict__ bv)
{
    extern __shared__ char smem[];
    const int z  = blockIdx.z;
    const int m0 = blockIdx.x * 128;
    const int n0 = blockIdx.y * 128;
    const float* X = g_Xt + (size_t)z * (M_ * D_);
    const float* W = g_Wt + (size_t)z * (D_ * D_);

    float c[4][4][4];
    gemm_core(smem,
        [&](int r, int kt, int ch) { return X + (size_t)(m0 + r) * D_ + kt * 32 + ch * 4; },
        [&](int r, int kt, int ch) { return W + (size_t)(n0 + r) * D_ + kt * 32 + ch * 4; },
        c);

    const float* bias = (z == 0) ? bq : (z == 1) ? bk : bv;
    const float qscale = (z == 0) ? 0.125f : 1.0f;
    float* Cs = (float*)smem;
    const int tid = threadIdx.x;

    if (z < 2) {
        float* outp = (z == 0) ? g_Qp : g_Kp;
        #pragma unroll 8
        for (int it = 0; it < 64; it++) {
            int idx = tid + it * 256;
            int r = idx >> 7, cc = idx & 127;
            int m = m0 + r, n = n0 + cc;
            int b = m >> 11, l = m & (L_ - 1);
            int h = n >> 6, hd = n & (HD_ - 1);
            int hdp = (hd & ~7) | kperm(hd & 7);
            float val = wmma::__float_to_tf32(Cs[r * 132 + cc] + bias[n]) * qscale;
            outp[(((size_t)(b * H_ + h)) * L_ + l) * HD_ + hdp] = val;
        }
    } else {
        // V pair-packed: [bh][l>>3][pair=l&3][hd][slot=(l&7)>>2]
        #pragma unroll 8
        for (int it = 0; it < 64; it++) {
            int idx = tid + it * 256;
            int r = idx >> 7, cc = idx & 127;
            int m = m0 + r, n = n0 + cc;
            int b = m >> 11, l = m & (L_ - 1);
            int h = n >> 6, hd = n & (HD_ - 1);
            int bh = b * H_ + h;
            float val = wmma::__float_to_tf32(Cs[r * 132 + cc] + bias[n]);
            size_t off = ((size_t)bh * (L_ / 8) + (l >> 3)) * 512
                       + (size_t)(l & 3) * 128 + hd * 2 + ((l & 7) >> 2);
            g_Vp[off] = val;
        }
    }
}

// ---------------------------------------------------------------------------
// Flash attention: register-resident, float2 fragment loads from permuted
// K (KPAD=72) and pair-packed V (pair stride 136). 2-stage cp.async, 2 CTAs/SM.
// ---------------------------------------------------------------------------
#define KPAD2 72
#define VPAIR 136
#define VGRP  (4 * VPAIR)                       // 544 floats per 8-row group
#define ATT_K_F (64 * KPAD2)                    // 4608
#define ATT_V_F (8 * VGRP)                      // 4352
#define ATT_STG_F (ATT_K_F + ATT_V_F)           // 8960
#define ATT_STG_B (ATT_STG_F * 4)               // 35840
#define NT_ (L_ / 64)

__global__ __launch_bounds__(256, 2) void attn_kernel(const unsigned char* __restrict__ mask)
{
    extern __shared__ char smem[];
    const unsigned int smem_u32 = (unsigned int)__cvta_generic_to_shared(smem);
    float* Ms = (float*)(smem + 2 * ATT_STG_B);

    const int q0   = blockIdx.x * 128;
    const int bh   = blockIdx.y;
    const int b    = bh >> 4;
    const int tid  = threadIdx.x;
    const int warp = tid >> 5;
    const int lane = tid & 31;
    const int qr   = lane >> 2;
    const int qq   = lane & 3;
    const int rowbase = q0 + warp * 16;

    const float* Kg0 = g_Kp + (size_t)bh * L_ * HD_;
    const float* Vg0 = g_Vp + (size_t)bh * (L_ / 8) * 512;

    for (int i = tid; i < L_; i += 256)
        Ms[i] = mask[b * L_ + i] ? -1e30f : 0.0f;

    // Q fragments (hd-permuted in gmem -> float2 pair loads)
    unsigned qa[8][4];
    {
        const float* Qg = g_Qp + ((size_t)bh * L_ + rowbase) * HD_;
        #pragma unroll
        for (int ks = 0; ks < 8; ks++) {
            float2 v0 = *(const float2*)(Qg + (size_t)qr * HD_ + ks * 8 + 2 * qq);
            float2 v1 = *(const float2*)(Qg + (size_t)(qr + 8) * HD_ + ks * 8 + 2 * qq);
            qa[ks][0] = __float_as_uint(v0.x);
            qa[ks][1] = __float_as_uint(v1.x);
            qa[ks][2] = __float_as_uint(v0.y);
            qa[ks][3] = __float_as_uint(v1.y);
        }
    }

    auto issue = [&](int s, int kt) {
        const int kbase = kt * 64;
        const unsigned int sb = smem_u32 + s * ATT_STG_B;
        #pragma unroll
        for (int it = 0; it < 4; it++) {
            int ck = tid + it * 256;          // 0..1023 K chunks
            int row = ck >> 4, colc = ck & 15;
            cpasync16(sb + (row * KPAD2 + colc * 4) * 4,
                      Kg0 + (size_t)(kbase + row) * HD_ + colc * 4);
            int grp = ck >> 7, pr = (ck >> 5) & 3, w = ck & 31;
            cpasync16(sb + (ATT_K_F + grp * VGRP + pr * VPAIR + w * 4) * 4,
                      Vg0 + (size_t)(kt * 8 + grp) * 512 + pr * 128 + w * 4);
        }
        cpcommit();
    };

    float oacc[8][4];
    #pragma unroll
    for (int nt = 0; nt < 8; nt++)
        #pragma unroll
        for (int i = 0; i < 4; i++) oacc[nt][i] = 0.0f;
    float m0 = -1e30f, m1 = -1e30f;
    float l0 = 0.0f,  l1 = 0.0f;

    issue(0, 0);
    issue(1, 1);

    const int srcA = (lane & 28) | (qq >> 1);
    const int srcB = srcA | 2;
    const bool odd = qq & 1;

    for (int kt = 0; kt < NT_; kt++) {
        if (kt < NT_ - 1) { cpwait<1>(); } else { cpwait<0>(); }
        __syncthreads();

        const float* Ks = (const float*)(smem + (kt & 1) * ATT_STG_B);
        const float* Vs = Ks + ATT_K_F;
        const int kbase = kt * 64;

        // S = Q K^T : float2 B-frag loads
        float sacc[8][4];
        #pragma unroll
        for (int nt = 0; nt < 8; nt++) {
            float cfr[4] = {0.0f, 0.0f, 0.0f, 0.0f};
            const float* kb = Ks + (nt * 8 + qr) * KPAD2;
            #pragma unroll
            for (int ks = 0; ks < 8; ks++) {
                float2 kv = *(const float2*)(kb + ks * 8 + 2 * qq);
                mma_tf32(cfr, qa[ks], __float_as_uint(kv.x), __float_as_uint(kv.y));
            }
            sacc[nt][0] = cfr[0]; sacc[nt][1] = cfr[1];
            sacc[nt][2] = cfr[2]; sacc[nt][3] = cfr[3];
        }

        // online softmax
        float mx0 = -1e30f, mx1 = -1e30f;
        #pragma unroll
        for (int nt = 0; nt < 8; nt++) {
            float ma = Ms[kbase + nt * 8 + 2 * qq];
            float mb = Ms[kbase + nt * 8 + 2 * qq + 1];
            sacc[nt][0] += ma; sacc[nt][1] += mb;
            sacc[nt][2] += ma; sacc[nt][3] += mb;
            mx0 = fmaxf(mx0, fmaxf(sacc[nt][0], sacc[nt][1]));
            mx1 = fmaxf(mx1, fmaxf(sacc[nt][2], sacc[nt][3]));
        }
        mx0 = fmaxf(mx0, __shfl_xor_sync(0xffffffffu, mx0, 1));
        mx0 = fmaxf(mx0, __shfl_xor_sync(0xffffffffu, mx0, 2));
        mx1 = fmaxf(mx1, __shfl_xor_sync(0xffffffffu, mx1, 1));
        mx1 = fmaxf(mx1, __shfl_xor_sync(0xffffffffu, mx1, 2));

        float nm0 = fmaxf(m0, mx0), nm1 = fmaxf(m1, mx1);
        float al0 = __expf(m0 - nm0), al1 = __expf(m1 - nm1);
        float ps0 = 0.0f, ps1 = 0.0f;
        #pragma unroll
        for (int nt = 0; nt < 8; nt++) {
            float p0 = __expf(sacc[nt][0] - nm0);
            float p1 = __expf(sacc[nt][1] - nm0);
            float p2 = __expf(sacc[nt][2] - nm1);
            float p3 = __expf(sacc[nt][3] - nm1);
            ps0 += p0 + p1; ps1 += p2 + p3;
            sacc[nt][0] = p0; sacc[nt][1] = p1;
            sacc[nt][2] = p2; sacc[nt][3] = p3;
        }
        ps0 += __shfl_xor_sync(0xffffffffu, ps0, 1);
        ps0 += __shfl_xor_sync(0xffffffffu, ps0, 2);
        ps1 += __shfl_xor_sync(0xffffffffu, ps1, 1);
        ps1 += __shfl_xor_sync(0xffffffffu, ps1, 2);
        l0 = l0 * al0 + ps0;
        l1 = l1 * al1 + ps1;
        m0 = nm0; m1 = nm1;
        #pragma unroll
        for (int nt = 0; nt < 8; nt++) {
            oacc[nt][0] *= al0; oacc[nt][1] *= al0;
            oacc[nt][2] *= al1; oacc[nt][3] *= al1;
        }

        // O += P V : P C->A via shuffles; V pair-packed float2 B-frags
        #pragma unroll
        for (int ks = 0; ks < 8; ks++) {
            float p0 = sacc[ks][0], p1 = sacc[ks][1];
            float p2 = sacc[ks][2], p3 = sacc[ks][3];
            float v0 = __shfl_sync(0xffffffffu, p0, srcA);
            float v1 = __shfl_sync(0xffffffffu, p1, srcA);
            float v2 = __shfl_sync(0xffffffffu, p2, srcA);
            float v3 = __shfl_sync(0xffffffffu, p3, srcA);
            float w0 = __shfl_sync(0xffffffffu, p0, srcB);
            float w1 = __shfl_sync(0xffffffffu, p1, srcB);
            float w2 = __shfl_sync(0xffffffffu, p2, srcB);
            float w3 = __shfl_sync(0xffffffffu, p3, srcB);
            unsigned pa[4];
            pa[0] = __float_as_uint(odd ? v1 : v0);
            pa[1] = __float_as_uint(odd ? v3 : v2);
            pa[2] = __float_as_uint(odd ? w1 : w0);
            pa[3] = __float_as_uint(odd ? w3 : w2);
            const float* vb = Vs + ks * VGRP + qq * VPAIR;
            #pragma unroll
            for (int nt = 0; nt < 8; nt++) {
                float2 vv = *(const float2*)(vb + (nt * 8 + qr) * 2);
                mma_tf32(oacc[nt], pa, __float_as_uint(vv.x), __float_as_uint(vv.y));
            }
        }
        __syncthreads();
        if (kt + 2 < NT_) issue(kt & 1, kt + 2);
    }

    // finalize: divide by l, tf32-round, write g_AO hd-PERMUTED
    {
        float inv0 = (l0 > 0.0f) ? 1.0f / l0 : 0.0f;
        float inv1 = (l1 > 0.0f) ? 1.0f / l1 : 0.0f;
        const int pc0 = kperm(2 * qq);
        const int pc1 = kperm(2 * qq + 1);
        float* o0 = g_AO + ((size_t)bh * L_ + rowbase + qr) * HD_;
        float* o1 = g_AO + ((size_t)bh * L_ + rowbase + qr + 8) * HD_;
        #pragma unroll
        for (int nt = 0; nt < 8; nt++) {
            o0[nt * 8 + pc0] = wmma::__float_to_tf32(oacc[nt][0] * inv0);
            o0[nt * 8 + pc1] = wmma::__float_to_tf32(oacc[nt][1] * inv0);
            o1[nt * 8 + pc0] = wmma::__float_to_tf32(oacc[nt][2] * inv1);
            o1[nt * 8 + pc1] = wmma::__float_to_tf32(oacc[nt][3] * inv1);
        }
    }
}

// ---------------------------------------------------------------------------
// Output projection: out = AO_merged @ Wo^T + bo (both operands k-permuted).
// ---------------------------------------------------------------------------
__global__ __launch_bounds__(256, 2) void oproj_kernel(
    const float* __restrict__ bo, float* __restrict__ out)
{
    extern __shared__ char smem[];
    const int m0 = blockIdx.x * 128;
    const int n0 = blockIdx.y * 128;
    const float* W = g_Wt + (size_t)3 * (D_ * D_);

    float c[4][4][4];
    gemm_core(smem,
        [&](int r, int kt, int ch) {
            int head = kt >> 1;
            int koff = (kt & 1) * 32;
            int m = m0 + r;
            int b = m >> 11, l = m & (L_ - 1);
            return g_AO + (((size_t)(b * H_ + head)) * L_ + l) * HD_ + koff + ch * 4;
        },
        [&](int r, int kt, int ch) { return W + (size_t)(n0 + r) * D_ + kt * 32 + ch * 4; },
        c);

    float* Cs = (float*)smem;
    const int tid = threadIdx.x;
    #pragma unroll 8
    for (int it = 0; it < 64; it++) {
        int idx = tid + it * 256;
        int r = idx >> 7, cc = idx & 127;
        int m = m0 + r, n = n0 + cc;
        out[(size_t)m * D_ + n] = Cs[r * 132 + cc] + bo[n];
    }
}

// ---------------------------------------------------------------------------
extern "C" void kernel_launch(void* const* d_in, const int* in_sizes, int n_in,
                              void* d_out, int out_size)
{
    const float* q    = (const float*)d_in[0];
    const float* k    = (const float*)d_in[1];
    const float* v    = (const float*)d_in[2];
    const unsigned char* mask = (const unsigned char*)d_in[3];
    const float* Wq   = (const float*)d_in[4];
    const float* bq   = (const float*)d_in[5];
    const float* Wk   = (const float*)d_in[6];
    const float* bk   = (const float*)d_in[7];
    const float* Wv   = (const float*)d_in[8];
    const float* bv   = (const float*)d_in[9];
    const float* Wo   = (const float*)d_in[10];
    const float* bo   = (const float*)d_in[11];
    float* out        = (float*)d_out;

    const int gemmSmem = 2 * GSTG_B;                   // 81920
    const int attnSmem = 2 * ATT_STG_B + L_ * 4;       // 71680 + 8192 = 79872

    cudaFuncSetAttribute(proj_kernel,  cudaFuncAttributeMaxDynamicSharedMemorySize, gemmSmem);
    cudaFuncSetAttribute(attn_kernel,  cudaFuncAttributeMaxDynamicSharedMemorySize, attnSmem);
    cudaFuncSetAttribute(oproj_kernel, cudaFuncAttributeMaxDynamicSharedMemorySize, gemmSmem);

    prep_kernel<<<(4 * D_ * D_ + 3 * M_ * D_) / (4 * 256), 256>>>(q, k, v, Wq, Wk, Wv, Wo);

    dim3 gProj(M_ / 128, D_ / 128, 3);
    proj_kernel<<<gProj, 256, gemmSmem>>>(bq, bk, bv);

    dim3 gAttn(L_ / 128, B_ * H_);
    attn_kernel<<<gAttn, 256, attnSmem>>>(mask);

    dim3 gOut(M_ / 128, D_ / 128);
    oproj_kernel<<<gOut, 256, gemmSmem>>>(bo, out);
}